// round 11
// baseline (speedup 1.0000x reference)
#include <cuda_runtime.h>
#include <cuda_fp16.h>
#include <math.h>

// Problem constants
#define BB   2
#define HH   16
#define SS   2048
#define DD   1024
#define DK   64
#define BHN  (BB*HH)      // 32
#define KEEP 1843         // int(2048*0.9)

typedef unsigned int u32;

// ---------------- scratch (device globals; no cudaMalloc allowed) ----------
__device__ float  g_qh[(size_t)BHN * SS * DK];      // [b,h,s,d]
__device__ float  g_kh[(size_t)BHN * SS * DK];
__device__ float  g_vh[(size_t)BHN * SS * DK];
__device__ __half g_vtmh[(size_t)BHN * DK * SS];    // masked V^T fp16 [b,h,d,s]
__device__ float  g_probs[(size_t)BHN * SS * SS];   // 512 MiB fp32 scores
__device__ __half g_probsh[(size_t)BHN * SS * SS];  // 256 MiB fp16 probs
__device__ float  g_part[(size_t)BHN * 32 * SS];    // colsum partials
__device__ float  g_mask[BHN * SS];
__device__ __half g_concath[(size_t)BB * SS * DD];  // fp16 concat [b,s,h*64+d]

// ============================================================================
// FFMA fp32 NT GEMM body (QK projections), double-buffered smem.
// ============================================================================
template<int MODE>
__device__ __forceinline__ void ffma_tile(
    const float* __restrict__ A, const float* __restrict__ B,
    float* __restrict__ C, const float* __restrict__ bias,
    int K, int lda, int ldb, int ldc, float alpha,
    float As[2][8][128], float Bs[2][8][128])
{
    const int m0 = blockIdx.y * 128;
    const int n0 = blockIdx.x * 128;
    const int tid = threadIdx.x;
    const int tx = tid & 15;
    const int ty = tid >> 4;
    const int lrow = tid >> 1;
    const int lcol = (tid & 1) * 4;

    float acc[8][8];
#pragma unroll
    for (int i = 0; i < 8; i++)
#pragma unroll
        for (int j = 0; j < 8; j++) acc[i][j] = 0.f;

    const float* Aptr = A + (size_t)(m0 + lrow) * lda + lcol;
    const float* Bptr = B + (size_t)(n0 + lrow) * ldb + lcol;

    {
        float4 av = *(const float4*)(Aptr);
        float4 bv = *(const float4*)(Bptr);
        As[0][lcol + 0][lrow] = av.x; As[0][lcol + 1][lrow] = av.y;
        As[0][lcol + 2][lrow] = av.z; As[0][lcol + 3][lrow] = av.w;
        Bs[0][lcol + 0][lrow] = bv.x; Bs[0][lcol + 1][lrow] = bv.y;
        Bs[0][lcol + 2][lrow] = bv.z; Bs[0][lcol + 3][lrow] = bv.w;
    }
    __syncthreads();

    int buf = 0;
    for (int k0 = 8; k0 < K; k0 += 8) {
        float4 av = *(const float4*)(Aptr + k0);
        float4 bv = *(const float4*)(Bptr + k0);
        const int nb = buf ^ 1;
        As[nb][lcol + 0][lrow] = av.x; As[nb][lcol + 1][lrow] = av.y;
        As[nb][lcol + 2][lrow] = av.z; As[nb][lcol + 3][lrow] = av.w;
        Bs[nb][lcol + 0][lrow] = bv.x; Bs[nb][lcol + 1][lrow] = bv.y;
        Bs[nb][lcol + 2][lrow] = bv.z; Bs[nb][lcol + 3][lrow] = bv.w;
#pragma unroll
        for (int kk = 0; kk < 8; kk++) {
            float a[8], b[8];
            *(float4*)(a)     = *(const float4*)&As[buf][kk][ty * 8];
            *(float4*)(a + 4) = *(const float4*)&As[buf][kk][ty * 8 + 4];
            *(float4*)(b)     = *(const float4*)&Bs[buf][kk][tx * 8];
            *(float4*)(b + 4) = *(const float4*)&Bs[buf][kk][tx * 8 + 4];
#pragma unroll
            for (int i = 0; i < 8; i++)
#pragma unroll
                for (int j = 0; j < 8; j++) acc[i][j] += a[i] * b[j];
        }
        __syncthreads();
        buf = nb;
    }
#pragma unroll
    for (int kk = 0; kk < 8; kk++) {
        float a[8], b[8];
        *(float4*)(a)     = *(const float4*)&As[buf][kk][ty * 8];
        *(float4*)(a + 4) = *(const float4*)&As[buf][kk][ty * 8 + 4];
        *(float4*)(b)     = *(const float4*)&Bs[buf][kk][tx * 8];
        *(float4*)(b + 4) = *(const float4*)&Bs[buf][kk][tx * 8 + 4];
#pragma unroll
        for (int i = 0; i < 8; i++)
#pragma unroll
            for (int j = 0; j < 8; j++) acc[i][j] += a[i] * b[j];
    }

    if (MODE == 0) {
#pragma unroll
        for (int i = 0; i < 8; i++) {
            int m = m0 + ty * 8 + i;
            float out[8];
#pragma unroll
            for (int j = 0; j < 8; j++) {
                int n = n0 + tx * 8 + j;
                out[j] = acc[i][j] * alpha + (bias ? bias[n] : 0.f);
            }
            float* crow = C + (size_t)m * ldc + n0 + tx * 8;
            *(float4*)(crow)     = *(float4*)(out);
            *(float4*)(crow + 4) = *(float4*)(out + 4);
        }
    } else {
#pragma unroll
        for (int i = 0; i < 8; i++) {
            int m = m0 + ty * 8 + i;
            int b = m >> 11;
            int s = m & (SS - 1);
#pragma unroll
            for (int j = 0; j < 8; j++) {
                int n = n0 + tx * 8 + j;
                int h = n >> 6;
                int d = n & 63;
                C[(((size_t)(b * HH + h)) * SS + s) * DK + d] =
                    acc[i][j] * alpha + (bias ? bias[n] : 0.f);
            }
        }
    }
}

// Q and K projections in one launch (blockIdx.z selects).
__global__ __launch_bounds__(256, 2)
void sgemm_qk(const float* __restrict__ q,  const float* __restrict__ Wq,
              const float* __restrict__ bq, float* __restrict__ qh,
              const float* __restrict__ k,  const float* __restrict__ Wk,
              const float* __restrict__ bk, float* __restrict__ kh)
{
    __shared__ float As[2][8][128];
    __shared__ float Bs[2][8][128];
    const float* A  = blockIdx.z ? k  : q;
    const float* B  = blockIdx.z ? Wk : Wq;
    const float* bi = blockIdx.z ? bk : bq;
    float*       C  = blockIdx.z ? kh : qh;
    ffma_tile<1>(A, B, C, bi, DD, DD, DD, 0, 1.f, As, Bs);
}

// ============================================================================
// fp16 mma primitive
// ============================================================================
static __device__ __forceinline__ void mma_f16(float* d, const u32* a, const u32* b) {
    asm volatile(
        "mma.sync.aligned.m16n8k16.row.col.f32.f16.f16.f32 "
        "{%0,%1,%2,%3}, {%4,%5,%6,%7}, {%8,%9}, {%0,%1,%2,%3};"
        : "+f"(d[0]), "+f"(d[1]), "+f"(d[2]), "+f"(d[3])
        : "r"(a[0]), "r"(a[1]), "r"(a[2]), "r"(a[3]), "r"(b[0]), "r"(b[1]));
}

// ============================================================================
// 3-way fp16 split: x = h1 + h2/2048 + h3/2048 (h2,h3 stored pre-scaled by s)
// ============================================================================
static __device__ __forceinline__ void split3(float x, __half& h1, __half& h2,
                                              __half& h3)
{
    h1 = __float2half_rn(x);
    float r1 = x - __half2float(h1);
    h2 = __float2half_rn(r1 * 2048.f);
    float r2 = r1 - __half2float(h2) * (1.f / 2048.f);
    h3 = __float2half_rn(r2 * 2048.f);
}

// ============================================================================
// Scores via fp16x6 emulation (fp32-grade): C = 0.125 * A @ B^T.
// CTA 128x64, BK=32, 8 warps 2(m)x4(n), warp tile 64x16 (NFR=2).
// P0 = A1B1 ; P1 = A1B2s + A2sB1 + A1B3s + A3sB1 + A2s(B2s/s); C = P0 + P1/s.
// ============================================================================
__device__ void scores_f16x6_body(const float* __restrict__ Aq,
                                  const float* __restrict__ Bk,
                                  float* __restrict__ C,
                                  char* smem_raw)
{
    typedef __half (*H40)[40];
    H40 A1 = (H40)(smem_raw);
    H40 A2 = (H40)(smem_raw + 10240);
    H40 A3 = (H40)(smem_raw + 20480);
    H40 B1 = (H40)(smem_raw + 30720);
    H40 B2 = (H40)(smem_raw + 35840);
    H40 B3 = (H40)(smem_raw + 40960);

    const int tid  = threadIdx.x;
    const int wid  = tid >> 5;
    const int lane = tid & 31;
    const int wm   = wid & 1;
    const int wn   = wid >> 1;       // 0..3
    const int qid  = lane >> 2;
    const int rid  = lane & 3;

    const int m0 = blockIdx.y * 128;
    const int n0 = blockIdx.x * 64;

    float acc0[4][2][4], acc1[4][2][4];
#pragma unroll
    for (int i = 0; i < 4; i++)
#pragma unroll
        for (int j = 0; j < 2; j++)
#pragma unroll
            for (int t = 0; t < 4; t++) { acc0[i][j][t] = 0.f; acc1[i][j][t] = 0.f; }

    const __half2 inv_s2 = __float2half2_rn(1.f / 2048.f);

#pragma unroll
    for (int c = 0; c < 2; c++) {
        const int k0 = c << 5;
        float4 va[4], vb[2];
#pragma unroll
        for (int i = 0; i < 4; i++) {
            int idx = tid + i * 256;              // 0..1023
            int r = idx >> 3, cc = (idx & 7) << 2;
            va[i] = *(const float4*)(Aq + (size_t)(m0 + r) * DK + k0 + cc);
        }
#pragma unroll
        for (int i = 0; i < 2; i++) {
            int idx = tid + i * 256;              // 0..511
            int r = idx >> 3, cc = (idx & 7) << 2;
            vb[i] = *(const float4*)(Bk + (size_t)(n0 + r) * DK + k0 + cc);
        }
        __syncthreads();
#pragma unroll
        for (int i = 0; i < 4; i++) {
            int idx = tid + i * 256;
            int r = idx >> 3, cc = (idx & 7) << 2;
            float xs[4] = {va[i].x, va[i].y, va[i].z, va[i].w};
#pragma unroll
            for (int t = 0; t < 4; t++)
                split3(xs[t], A1[r][cc + t], A2[r][cc + t], A3[r][cc + t]);
        }
#pragma unroll
        for (int i = 0; i < 2; i++) {
            int idx = tid + i * 256;
            int r = idx >> 3, cc = (idx & 7) << 2;
            float xs[4] = {vb[i].x, vb[i].y, vb[i].z, vb[i].w};
#pragma unroll
            for (int t = 0; t < 4; t++)
                split3(xs[t], B1[r][cc + t], B2[r][cc + t], B3[r][cc + t]);
        }
        __syncthreads();

#pragma unroll
        for (int kk = 0; kk < 32; kk += 16) {
            u32 a1[4][4], a2[4][4], a3[4][4];
#pragma unroll
            for (int mt = 0; mt < 4; mt++) {
                int row = wm * 64 + mt * 16 + qid;
                a1[mt][0] = *(const u32*)&A1[row    ][kk + rid * 2];
                a1[mt][1] = *(const u32*)&A1[row + 8][kk + rid * 2];
                a1[mt][2] = *(const u32*)&A1[row    ][kk + rid * 2 + 8];
                a1[mt][3] = *(const u32*)&A1[row + 8][kk + rid * 2 + 8];
                a2[mt][0] = *(const u32*)&A2[row    ][kk + rid * 2];
                a2[mt][1] = *(const u32*)&A2[row + 8][kk + rid * 2];
                a2[mt][2] = *(const u32*)&A2[row    ][kk + rid * 2 + 8];
                a2[mt][3] = *(const u32*)&A2[row + 8][kk + rid * 2 + 8];
                a3[mt][0] = *(const u32*)&A3[row    ][kk + rid * 2];
                a3[mt][1] = *(const u32*)&A3[row + 8][kk + rid * 2];
                a3[mt][2] = *(const u32*)&A3[row    ][kk + rid * 2 + 8];
                a3[mt][3] = *(const u32*)&A3[row + 8][kk + rid * 2 + 8];
            }
            u32 b1[2][2], b2[2][2], b3[2][2], b2r[2][2];
#pragma unroll
            for (int nt = 0; nt < 2; nt++) {
                int col = wn * 16 + nt * 8 + qid;
                b1[nt][0] = *(const u32*)&B1[col][kk + rid * 2];
                b1[nt][1] = *(const u32*)&B1[col][kk + rid * 2 + 8];
                b2[nt][0] = *(const u32*)&B2[col][kk + rid * 2];
                b2[nt][1] = *(const u32*)&B2[col][kk + rid * 2 + 8];
                b3[nt][0] = *(const u32*)&B3[col][kk + rid * 2];
                b3[nt][1] = *(const u32*)&B3[col][kk + rid * 2 + 8];
                __half2 t0 = __hmul2(*(__half2*)&b2[nt][0], inv_s2);
                __half2 t1 = __hmul2(*(__half2*)&b2[nt][1], inv_s2);
                b2r[nt][0] = *(u32*)&t0;
                b2r[nt][1] = *(u32*)&t1;
            }
#pragma unroll
            for (int mt = 0; mt < 4; mt++)
#pragma unroll
                for (int nt = 0; nt < 2; nt++) {
                    mma_f16(acc0[mt][nt], a1[mt], b1[nt]);
                    mma_f16(acc1[mt][nt], a1[mt], b2[nt]);
                    mma_f16(acc1[mt][nt], a2[mt], b1[nt]);
                    mma_f16(acc1[mt][nt], a1[mt], b3[nt]);
                    mma_f16(acc1[mt][nt], a3[mt], b1[nt]);
                    mma_f16(acc1[mt][nt], a2[mt], b2r[nt]);
                }
        }
        __syncthreads();
    }

    const float S = 1.f / 2048.f;
#pragma unroll
    for (int mt = 0; mt < 4; mt++) {
        int r0 = m0 + wm * 64 + mt * 16 + qid;
        int r1 = r0 + 8;
#pragma unroll
        for (int nt = 0; nt < 2; nt++) {
            int cb = n0 + wn * 16 + nt * 8 + rid * 2;
            float v0 = (acc0[mt][nt][0] + acc1[mt][nt][0] * S) * 0.125f;
            float v1 = (acc0[mt][nt][1] + acc1[mt][nt][1] * S) * 0.125f;
            float v2 = (acc0[mt][nt][2] + acc1[mt][nt][2] * S) * 0.125f;
            float v3 = (acc0[mt][nt][3] + acc1[mt][nt][3] * S) * 0.125f;
            *(float2*)(C + (size_t)r0 * SS + cb) = make_float2(v0, v1);
            *(float2*)(C + (size_t)r1 * SS + cb) = make_float2(v2, v3);
        }
    }
}

// ============================================================================
// fp16x3 split GEMM body (V projection): 22-bit accurate.
// ============================================================================
__device__ void hgemm3_body(const float* __restrict__ Ag,
                            const float* __restrict__ Bg,
                            float* __restrict__ Cg,
                            const float* __restrict__ bias,
                            int m0, int n0, char* smem_raw)
{
    typedef __half (*HArr)[40];
    HArr Ah = (HArr)(smem_raw);
    HArr Al = (HArr)(smem_raw + 10240);
    HArr Bh = (HArr)(smem_raw + 20480);
    HArr Bl = (HArr)(smem_raw + 30720);

    const int tid  = threadIdx.x;
    const int wid  = tid >> 5;
    const int lane = tid & 31;
    const int wm   = wid & 1;
    const int wn   = wid >> 1;
    const int qid  = lane >> 2;
    const int rid  = lane & 3;

    float acc[4][4][4];
#pragma unroll
    for (int i = 0; i < 4; i++)
#pragma unroll
        for (int j = 0; j < 4; j++)
#pragma unroll
            for (int t = 0; t < 4; t++) acc[i][j][t] = 0.f;

    for (int c = 0; c < DD / 32; c++) {
        const int k0 = c << 5;
        float4 va[4], vb[4];
#pragma unroll
        for (int i = 0; i < 4; i++) {
            int idx = tid + i * 256;
            int r = idx >> 3, cc = (idx & 7) << 2;
            va[i] = *(const float4*)(Ag + (size_t)(m0 + r) * DD + k0 + cc);
            vb[i] = *(const float4*)(Bg + (size_t)(n0 + r) * DD + k0 + cc);
        }
        __syncthreads();
#pragma unroll
        for (int i = 0; i < 4; i++) {
            int idx = tid + i * 256;
            int r = idx >> 3, cc = (idx & 7) << 2;
            float xa[4] = {va[i].x, va[i].y, va[i].z, va[i].w};
            float xb[4] = {vb[i].x, vb[i].y, vb[i].z, vb[i].w};
#pragma unroll
            for (int t = 0; t < 4; t++) {
                __half h = __float2half_rn(xa[t]);
                Ah[r][cc + t] = h;
                Al[r][cc + t] = __float2half_rn(xa[t] - __half2float(h));
                __half g = __float2half_rn(xb[t]);
                Bh[r][cc + t] = g;
                Bl[r][cc + t] = __float2half_rn(xb[t] - __half2float(g));
            }
        }
        __syncthreads();

#pragma unroll
        for (int kk = 0; kk < 32; kk += 16) {
            u32 ah[4][4], al[4][4], bh[4][2], bl[4][2];
#pragma unroll
            for (int mt = 0; mt < 4; mt++) {
                int row = wm * 64 + mt * 16 + qid;
                ah[mt][0] = *(const u32*)&Ah[row    ][kk + rid * 2];
                ah[mt][1] = *(const u32*)&Ah[row + 8][kk + rid * 2];
                ah[mt][2] = *(const u32*)&Ah[row    ][kk + rid * 2 + 8];
                ah[mt][3] = *(const u32*)&Ah[row + 8][kk + rid * 2 + 8];
                al[mt][0] = *(const u32*)&Al[row    ][kk + rid * 2];
                al[mt][1] = *(const u32*)&Al[row + 8][kk + rid * 2];
                al[mt][2] = *(const u32*)&Al[row    ][kk + rid * 2 + 8];
                al[mt][3] = *(const u32*)&Al[row + 8][kk + rid * 2 + 8];
            }
#pragma unroll
            for (int nt = 0; nt < 4; nt++) {
                int col = wn * 32 + nt * 8 + qid;
                bh[nt][0] = *(const u32*)&Bh[col][kk + rid * 2];
                bh[nt][1] = *(const u32*)&Bh[col][kk + rid * 2 + 8];
                bl[nt][0] = *(const u32*)&Bl[col][kk + rid * 2];
                bl[nt][1] = *(const u32*)&Bl[col][kk + rid * 2 + 8];
            }
#pragma unroll
            for (int mt = 0; mt < 4; mt++)
#pragma unroll
                for (int nt = 0; nt < 4; nt++) {
                    mma_f16(acc[mt][nt], ah[mt], bh[nt]);
                    mma_f16(acc[mt][nt], ah[mt], bl[nt]);
                    mma_f16(acc[mt][nt], al[mt], bh[nt]);
                }
        }
        __syncthreads();
    }

#pragma unroll
    for (int mt = 0; mt < 4; mt++) {
        int r0 = m0 + wm * 64 + mt * 16 + qid;
        int r1 = r0 + 8;
#pragma unroll
        for (int nt = 0; nt < 4; nt++) {
            int cb = n0 + wn * 32 + nt * 8 + rid * 2;
            float b0 = bias[cb], b1 = bias[cb + 1];
            float v0 = acc[mt][nt][0] + b0;
            float v1 = acc[mt][nt][1] + b1;
            float v2 = acc[mt][nt][2] + b0;
            float v3 = acc[mt][nt][3] + b1;
            int h = cb >> 6, d = cb & 63;
            int b0i = r0 >> 11, s0i = r0 & (SS - 1);
            int b1i = r1 >> 11, s1i = r1 & (SS - 1);
            *(float2*)(Cg + (((size_t)(b0i * HH + h)) * SS + s0i) * DK + d) =
                make_float2(v0, v1);
            *(float2*)(Cg + (((size_t)(b1i * HH + h)) * SS + s1i) * DK + d) =
                make_float2(v2, v3);
        }
    }
}

// ============================================================================
// Fused launch: scores (fp16x6, z<32) + V projection (fp16x3, z==32).
// ============================================================================
__global__ __launch_bounds__(256)
void sgemm_scores_vproj(const float* __restrict__ qh, const float* __restrict__ kh,
                        float* __restrict__ probs,
                        const float* __restrict__ v, const float* __restrict__ Wv,
                        const float* __restrict__ bv, float* __restrict__ vh)
{
    __shared__ __align__(16) char smem_raw[46080];

    if (blockIdx.z < 32) {
        const size_t z = blockIdx.z;
        scores_f16x6_body(qh + z * SS * DK, kh + z * SS * DK,
                          probs + z * SS * SS, smem_raw);
    } else {
        // z == 32: 256 CTAs of V projection (32 m-tiles x 8 n-tiles)
        int flat = blockIdx.y * 32 + blockIdx.x;   // grid x is 32 wide now
        if (flat >= 256) return;
        int m0 = (flat >> 3) * 128;
        int n0 = (flat & 7) * 128;
        hgemm3_body(v, Wv, vh, bv, m0, n0, smem_raw);
    }
}

// ============================================================================
// fp16 m16n8k16 NT GEMM (value path). A fp16, B fp16 or fp32(cvt), f32 acc.
// mode 3: AV -> fp16 concat scatter (z=(b,h)); mode 0: fp32 C + bias.
// ============================================================================
template<int NT, bool B_F32>
__global__ __launch_bounds__(256)
void hgemm_nt(const __half* __restrict__ Ag, const void* __restrict__ Bv,
              float* __restrict__ Cf, __half* __restrict__ Ch,
              const float* __restrict__ bias,
              int K, int lda, int ldb, int ldc,
              long long sA, long long sB,
              int mode)
{
    __shared__ __half As[128][56];
    __shared__ __half Bs[NT][56];

    const int tid  = threadIdx.x;
    const int wid  = tid >> 5;
    const int lane = tid & 31;
    const int wm   = wid & 1;
    const int wn   = wid >> 1;
    const int qid  = lane >> 2;
    const int rid  = lane & 3;

    constexpr int WN  = NT / 4;      // 32 or 16
    constexpr int NFR = WN / 8;      // 4 or 2

    const __half* A = Ag + (size_t)blockIdx.z * sA;
    const int m0 = blockIdx.y * 128;
    const int n0 = blockIdx.x * NT;

    float acc[4][NFR][4];
#pragma unroll
    for (int i = 0; i < 4; i++)
#pragma unroll
        for (int j = 0; j < NFR; j++)
#pragma unroll
            for (int t = 0; t < 4; t++) acc[i][j][t] = 0.f;

    const int nc = K >> 5;
    for (int c = 0; c < nc; c++) {
        const int k0 = c << 5;
        uint4 va[2];
#pragma unroll
        for (int i = 0; i < 2; i++) {
            int idx = tid + i * 256;
            int r = idx >> 2, seg = (idx & 3) << 3;
            va[i] = *(const uint4*)(A + (size_t)(m0 + r) * lda + k0 + seg);
        }
        if (B_F32) {
            const float* B = (const float*)Bv + (size_t)blockIdx.z * sB;
            constexpr int BI = (NT * 32) / (4 * 256);
            float4 vb[BI];
#pragma unroll
            for (int i = 0; i < BI; i++) {
                int idx = tid + i * 256;
                int r = idx >> 3, seg = (idx & 7) << 2;
                vb[i] = *(const float4*)(B + (size_t)(n0 + r) * ldb + k0 + seg);
            }
            __syncthreads();
#pragma unroll
            for (int i = 0; i < 2; i++) {
                int idx = tid + i * 256;
                int r = idx >> 2, seg = (idx & 3) << 3;
                *(uint4*)&As[r][seg] = va[i];
            }
#pragma unroll
            for (int i = 0; i < BI; i++) {
                int idx = tid + i * 256;
                int r = idx >> 3, seg = (idx & 7) << 2;
                *(__half2*)&Bs[r][seg]     = __floats2half2_rn(vb[i].x, vb[i].y);
                *(__half2*)&Bs[r][seg + 2] = __floats2half2_rn(vb[i].z, vb[i].w);
            }
        } else {
            const __half* B = (const __half*)Bv + (size_t)blockIdx.z * sB;
            constexpr int BI = (NT * 32) / (8 * 256) > 0 ? (NT * 32) / (8 * 256) : 1;
            uint4 vb[BI];
#pragma unroll
            for (int i = 0; i < BI; i++) {
                int idx = tid + i * 256;
                int r = idx >> 2, seg = (idx & 3) << 3;
                vb[i] = *(const uint4*)(B + (size_t)(n0 + r) * ldb + k0 + seg);
            }
            __syncthreads();
#pragma unroll
            for (int i = 0; i < 2; i++) {
                int idx = tid + i * 256;
                int r = idx >> 2, seg = (idx & 3) << 3;
                *(uint4*)&As[r][seg] = va[i];
            }
#pragma unroll
            for (int i = 0; i < BI; i++) {
                int idx = tid + i * 256;
                int r = idx >> 2, seg = (idx & 3) << 3;
                *(uint4*)&Bs[r][seg] = vb[i];
            }
        }
        __syncthreads();

#pragma unroll
        for (int kk = 0; kk < 32; kk += 16) {
            u32 af[4][4], bf[NFR][2];
#pragma unroll
            for (int mt = 0; mt < 4; mt++) {
                int row = wm * 64 + mt * 16 + qid;
                af[mt][0] = *(const u32*)&As[row    ][kk + rid * 2];
                af[mt][1] = *(const u32*)&As[row + 8][kk + rid * 2];
                af[mt][2] = *(const u32*)&As[row    ][kk + rid * 2 + 8];
                af[mt][3] = *(const u32*)&As[row + 8][kk + rid * 2 + 8];
            }
#pragma unroll
            for (int nt = 0; nt < NFR; nt++) {
                int col = wn * WN + nt * 8 + qid;
                bf[nt][0] = *(const u32*)&Bs[col][kk + rid * 2];
                bf[nt][1] = *(const u32*)&Bs[col][kk + rid * 2 + 8];
            }
#pragma unroll
            for (int mt = 0; mt < 4; mt++)
#pragma unroll
                for (int nt = 0; nt < NFR; nt++)
                    mma_f16(acc[mt][nt], af[mt], bf[nt]);
        }
        __syncthreads();
    }

#pragma unroll
    for (int mt = 0; mt < 4; mt++) {
        int r0 = m0 + wm * 64 + mt * 16 + qid;
        int r1 = r0 + 8;
#pragma unroll
        for (int nt = 0; nt < NFR; nt++) {
            int cb = n0 + wn * WN + nt * 8 + rid * 2;
            float v0 = acc[mt][nt][0];
            float v1 = acc[mt][nt][1];
            float v2 = acc[mt][nt][2];
            float v3 = acc[mt][nt][3];
            if (mode == 0) {
                float b0 = bias[cb], b1 = bias[cb + 1];
                *(float2*)(Cf + (size_t)r0 * ldc + cb) = make_float2(v0 + b0, v1 + b1);
                *(float2*)(Cf + (size_t)r1 * ldc + cb) = make_float2(v2 + b0, v3 + b1);
            } else {
                int z = blockIdx.z, b = z >> 4, h = z & 15;
                *(__half2*)(Ch + ((size_t)b * SS + r0) * DD + h * DK + cb) =
                    __floats2half2_rn(v0, v1);
                *(__half2*)(Ch + ((size_t)b * SS + r1) * DD + h * DK + cb) =
                    __floats2half2_rn(v2, v3);
            }
        }
    }
}

// ============================================================================
// Fused softmax + colsum partials; fp16 probs out. Two rows per iteration.
// ============================================================================
__global__ __launch_bounds__(256)
void softmax_colsum_kernel(const float* __restrict__ scores,
                           __half* __restrict__ probsh,
                           float* __restrict__ part)
{
    __shared__ float redA[2][8];
    __shared__ float redB[2][8];
    const int rb = blockIdx.x;   // 0..31
    const int bh = blockIdx.y;
    const int tid = threadIdx.x;
    const int wid = tid >> 5, lane = tid & 31;

    float cs[8];
#pragma unroll
    for (int i = 0; i < 8; i++) cs[i] = 0.f;

    for (int r = 0; r < 64; r += 2) {
        const float* row0 = scores + ((size_t)bh * SS + rb * 64 + r) * SS + tid * 8;
        const float* row1 = row0 + SS;
        float x0[8], x1[8];
        *(float4*)(x0)     = *(const float4*)(row0);
        *(float4*)(x0 + 4) = *(const float4*)(row0 + 4);
        *(float4*)(x1)     = *(const float4*)(row1);
        *(float4*)(x1 + 4) = *(const float4*)(row1 + 4);

        float m0 = x0[0], m1 = x1[0];
#pragma unroll
        for (int i = 1; i < 8; i++) { m0 = fmaxf(m0, x0[i]); m1 = fmaxf(m1, x1[i]); }
#pragma unroll
        for (int o = 16; o > 0; o >>= 1) {
            m0 = fmaxf(m0, __shfl_xor_sync(0xFFFFFFFF, m0, o));
            m1 = fmaxf(m1, __shfl_xor_sync(0xFFFFFFFF, m1, o));
        }
        if (lane == 0) { redA[0][wid] = m0; redA[1][wid] = m1; }
        __syncthreads();
        m0 = redA[0][0]; m1 = redA[1][0];
#pragma unroll
        for (int w = 1; w < 8; w++) {
            m0 = fmaxf(m0, redA[0][w]);
            m1 = fmaxf(m1, redA[1][w]);
        }

        float s0 = 0.f, s1 = 0.f;
#pragma unroll
        for (int i = 0; i < 8; i++) {
            x0[i] = __expf(x0[i] - m0); s0 += x0[i];
            x1[i] = __expf(x1[i] - m1); s1 += x1[i];
        }
#pragma unroll
        for (int o = 16; o > 0; o >>= 1) {
            s0 += __shfl_xor_sync(0xFFFFFFFF, s0, o);
            s1 += __shfl_xor_sync(0xFFFFFFFF, s1, o);
        }
        if (lane == 0) { redB[0][wid] = s0; redB[1][wid] = s1; }
        __syncthreads();
        s0 = redB[0][0]; s1 = redB[1][0];
#pragma unroll
        for (int w = 1; w < 8; w++) { s0 += redB[0][w]; s1 += redB[1][w]; }
        float inv0 = 1.0f / s0;
        float inv1 = 1.0f / s1;

        __half2 h0[4], h1[4];
#pragma unroll
        for (int i = 0; i < 8; i += 2) {
            float p0 = x0[i] * inv0, p1 = x0[i + 1] * inv0;
            cs[i] += p0; cs[i + 1] += p1;
            h0[i >> 1] = __floats2half2_rn(p0, p1);
        }
#pragma unroll
        for (int i = 0; i < 8; i += 2) {
            float p0 = x1[i] * inv1, p1 = x1[i + 1] * inv1;
            cs[i] += p0; cs[i + 1] += p1;
            h1[i >> 1] = __floats2half2_rn(p0, p1);
        }
        *(uint4*)(probsh + ((size_t)bh * SS + rb * 64 + r) * SS + tid * 8) =
            *(uint4*)h0;
        *(uint4*)(probsh + ((size_t)bh * SS + rb * 64 + r + 1) * SS + tid * 8) =
            *(uint4*)h1;
        __syncthreads();
    }
#pragma unroll
    for (int i = 0; i < 8; i++)
        part[((size_t)bh * 32 + rb) * SS + tid * 8 + i] = cs[i];
}

// ============================================================================
// Fused colsum-reduce + top-k mask (bitonic sort). One block per (b,h).
// ============================================================================
__global__ void topk_mask_kernel(const float* __restrict__ part,
                                 float* __restrict__ mask)
{
    __shared__ float s[SS];
    __shared__ float cs_sh[SS];
    const int bh = blockIdx.x;
    const int tid = threadIdx.x; // 1024

    for (int j = tid; j < SS; j += 1024) {
        float sum = 0.f;
#pragma unroll
        for (int rb = 0; rb < 32; rb++)
            sum += part[((size_t)bh * 32 + rb) * SS + j];
        s[j] = sum;
        cs_sh[j] = sum;
    }
    __syncthreads();

    for (int ksz = 2; ksz <= SS; ksz <<= 1) {
        for (int j = ksz >> 1; j > 0; j >>= 1) {
            for (int i = tid; i < SS; i += 1024) {
                int p = i ^ j;
                if (p > i) {
                    bool up = ((i & ksz) == 0);
                    float a = s[i], b = s[p];
                    if ((a > b) == up) { s[i] = b; s[p] = a; }
                }
            }
            __syncthreads();
        }
    }
    float thr = s[SS - KEEP];
    mask[bh * SS + tid]        = (cs_sh[tid]        >= thr) ? 1.f : 0.f;
    mask[bh * SS + tid + 1024] = (cs_sh[tid + 1024] >= thr) ? 1.f : 0.f;
}

// ============================================================================
// Masked transpose to fp16: vtmh[bh][d][s] = fp16(vh[bh][s][d] * mask[bh][s])
// ============================================================================
__global__ void vt_mask_kernel(const float* __restrict__ vh,
                               const float* __restrict__ mask,
                               __half* __restrict__ vtmh)
{
    __shared__ float t[32][33];
    const int bh = blockIdx.z;
    const int s0 = blockIdx.x * 32;
    const int d0 = blockIdx.y * 32;
    const int lx = threadIdx.x & 31;
    const int ly = threadIdx.x >> 5;
    for (int i = ly; i < 32; i += 8)
        t[i][lx] = vh[((size_t)bh * SS + s0 + i) * DK + d0 + lx] * mask[bh * SS + s0 + i];
    __syncthreads();
    for (int i = ly; i < 32; i += 8)
        vtmh[((size_t)bh * DK + d0 + i) * SS + s0 + lx] = __float2half_rn(t[lx][i]);
}

// ---------------------------------------------------------------------------
extern "C" void kernel_launch(void* const* d_in, const int* in_sizes, int n_in,
                              void* d_out, int out_size)
{
    (void)in_sizes; (void)n_in; (void)out_size;
    const float* q  = (const float*)d_in[0];
    const float* k  = (const float*)d_in[1];
    const float* v  = (const float*)d_in[2];
    const float* Wq = (const float*)d_in[3];
    const float* bq = (const float*)d_in[4];
    const float* Wk = (const float*)d_in[5];
    const float* bk = (const float*)d_in[6];
    const float* Wv = (const float*)d_in[7];
    const float* bv = (const float*)d_in[8];
    const float* Wo = (const float*)d_in[9];
    const float* bo = (const float*)d_in[10];
    float* out = (float*)d_out;

    float *qh, *kh, *vh, *probs, *part, *mask;
    __half *vtmh, *probsh, *concath;
    cudaGetSymbolAddress((void**)&qh,      g_qh);
    cudaGetSymbolAddress((void**)&kh,      g_kh);
    cudaGetSymbolAddress((void**)&vh,      g_vh);
    cudaGetSymbolAddress((void**)&vtmh,    g_vtmh);
    cudaGetSymbolAddress((void**)&probs,   g_probs);
    cudaGetSymbolAddress((void**)&probsh,  g_probsh);
    cudaGetSymbolAddress((void**)&part,    g_part);
    cudaGetSymbolAddress((void**)&mask,    g_mask);
    cudaGetSymbolAddress((void**)&concath, g_concath);

    // Q + K projections in one launch (fp32 FFMA, selection-exact)
    dim3 gqk(DD / 128, (BB * SS) / 128, 2);
    sgemm_qk<<<gqk, 256>>>(q, Wq, bq, qh, k, Wk, bk, kh);

    // Fused: scores (fp16x6 emulation, z<32) + V projection (fp16x3, z==32)
    dim3 gsv(SS / 64, SS / 128, BHN + 1);
    sgemm_scores_vproj<<<gsv, 256>>>(qh, kh, probs, v, Wv, bv, vh);

    // Fused softmax + colsum partials (fp16 probs out)
    softmax_colsum_kernel<<<dim3(32, BHN), 256>>>(probs, probsh, part);

    // Fused colsum reduce + top-k mask
    topk_mask_kernel<<<BHN, 1024>>>(part, mask);

    // Masked V transpose -> fp16 vtmh[bh][d][s]
    vt_mask_kernel<<<dim3(SS / 32, DK / 32, BHN), 256>>>(vh, mask, vtmh);

    // AV (fp16 mma): per (b,h) 2048x64x2048 -> fp16 concat
    dim3 gav(1, SS / 128, BHN);
    hgemm_nt<64, false><<<gav, 256>>>(probsh, vtmh, nullptr, concath, nullptr,
                                      SS, SS, SS, 0,
                                      (long long)SS * SS, (long long)DK * SS, 3);

    // Output projection (fp16 mma, Wo cvt on load): fp32 out + bias
    dim3 gop(DD / 128, (BB * SS) / 128, 1);
    hgemm_nt<128, true><<<gop, 256>>>(concath, Wo, out, nullptr, bo,
                                      DD, DD, DD, DD, 0, 0, 0);
}

// round 12
// speedup vs baseline: 1.0490x; 1.0490x over previous
#include <cuda_runtime.h>
#include <cuda_fp16.h>
#include <math.h>

// Problem constants
#define BB   2
#define HH   16
#define SS   2048
#define DD   1024
#define DK   64
#define BHN  (BB*HH)      // 32
#define KEEP 1843         // int(2048*0.9)

typedef unsigned int u32;

// ---------------- scratch (device globals; no cudaMalloc allowed) ----------
__device__ float  g_qh[(size_t)BHN * SS * DK];      // [b,h,s,d]
__device__ float  g_kh[(size_t)BHN * SS * DK];
__device__ float  g_vh[(size_t)BHN * SS * DK];
__device__ __half g_vtmh[(size_t)BHN * DK * SS];    // masked V^T fp16 [b,h,d,s]
__device__ float  g_probs[(size_t)BHN * SS * SS];   // 512 MiB fp32 scores
__device__ __half g_probsh[(size_t)BHN * SS * SS];  // 256 MiB fp16 probs
__device__ float  g_part[(size_t)BHN * 32 * SS];    // colsum partials
__device__ float  g_mask[BHN * SS];
__device__ __half g_concath[(size_t)BB * SS * DD];  // fp16 concat [b,s,h*64+d]

// ============================================================================
// FFMA fp32 NT GEMM body, double-buffered smem; m0/n0 passed in.
// Accumulation order identical to R1..R11 => bitwise-same results.
// MODE 0: row-major C (ldc); MODE 1: head-scatter [b,h,s,d].
// ============================================================================
template<int MODE>
__device__ __forceinline__ void ffma_tile(
    const float* __restrict__ A, const float* __restrict__ B,
    float* __restrict__ C, const float* __restrict__ bias,
    int K, int lda, int ldb, int ldc, float alpha, int m0, int n0,
    float As[2][8][128], float Bs[2][8][128])
{
    const int tid = threadIdx.x;
    const int tx = tid & 15;
    const int ty = tid >> 4;
    const int lrow = tid >> 1;
    const int lcol = (tid & 1) * 4;

    float acc[8][8];
#pragma unroll
    for (int i = 0; i < 8; i++)
#pragma unroll
        for (int j = 0; j < 8; j++) acc[i][j] = 0.f;

    const float* Aptr = A + (size_t)(m0 + lrow) * lda + lcol;
    const float* Bptr = B + (size_t)(n0 + lrow) * ldb + lcol;

    {
        float4 av = *(const float4*)(Aptr);
        float4 bv = *(const float4*)(Bptr);
        As[0][lcol + 0][lrow] = av.x; As[0][lcol + 1][lrow] = av.y;
        As[0][lcol + 2][lrow] = av.z; As[0][lcol + 3][lrow] = av.w;
        Bs[0][lcol + 0][lrow] = bv.x; Bs[0][lcol + 1][lrow] = bv.y;
        Bs[0][lcol + 2][lrow] = bv.z; Bs[0][lcol + 3][lrow] = bv.w;
    }
    __syncthreads();

    int buf = 0;
    for (int k0 = 8; k0 < K; k0 += 8) {
        float4 av = *(const float4*)(Aptr + k0);
        float4 bv = *(const float4*)(Bptr + k0);
        const int nb = buf ^ 1;
        As[nb][lcol + 0][lrow] = av.x; As[nb][lcol + 1][lrow] = av.y;
        As[nb][lcol + 2][lrow] = av.z; As[nb][lcol + 3][lrow] = av.w;
        Bs[nb][lcol + 0][lrow] = bv.x; Bs[nb][lcol + 1][lrow] = bv.y;
        Bs[nb][lcol + 2][lrow] = bv.z; Bs[nb][lcol + 3][lrow] = bv.w;
#pragma unroll
        for (int kk = 0; kk < 8; kk++) {
            float a[8], b[8];
            *(float4*)(a)     = *(const float4*)&As[buf][kk][ty * 8];
            *(float4*)(a + 4) = *(const float4*)&As[buf][kk][ty * 8 + 4];
            *(float4*)(b)     = *(const float4*)&Bs[buf][kk][tx * 8];
            *(float4*)(b + 4) = *(const float4*)&Bs[buf][kk][tx * 8 + 4];
#pragma unroll
            for (int i = 0; i < 8; i++)
#pragma unroll
                for (int j = 0; j < 8; j++) acc[i][j] += a[i] * b[j];
        }
        __syncthreads();
        buf = nb;
    }
#pragma unroll
    for (int kk = 0; kk < 8; kk++) {
        float a[8], b[8];
        *(float4*)(a)     = *(const float4*)&As[buf][kk][ty * 8];
        *(float4*)(a + 4) = *(const float4*)&As[buf][kk][ty * 8 + 4];
        *(float4*)(b)     = *(const float4*)&Bs[buf][kk][tx * 8];
        *(float4*)(b + 4) = *(const float4*)&Bs[buf][kk][tx * 8 + 4];
#pragma unroll
        for (int i = 0; i < 8; i++)
#pragma unroll
            for (int j = 0; j < 8; j++) acc[i][j] += a[i] * b[j];
    }

    if (MODE == 0) {
#pragma unroll
        for (int i = 0; i < 8; i++) {
            int m = m0 + ty * 8 + i;
            float out[8];
#pragma unroll
            for (int j = 0; j < 8; j++) {
                int n = n0 + tx * 8 + j;
                out[j] = acc[i][j] * alpha + (bias ? bias[n] : 0.f);
            }
            float* crow = C + (size_t)m * ldc + n0 + tx * 8;
            *(float4*)(crow)     = *(float4*)(out);
            *(float4*)(crow + 4) = *(float4*)(out + 4);
        }
    } else {
#pragma unroll
        for (int i = 0; i < 8; i++) {
            int m = m0 + ty * 8 + i;
            int b = m >> 11;
            int s = m & (SS - 1);
#pragma unroll
            for (int j = 0; j < 8; j++) {
                int n = n0 + tx * 8 + j;
                int h = n >> 6;
                int d = n & 63;
                C[(((size_t)(b * HH + h)) * SS + s) * DK + d] =
                    acc[i][j] * alpha + (bias ? bias[n] : 0.f);
            }
        }
    }
}

// ============================================================================
// fp16 mma primitive
// ============================================================================
static __device__ __forceinline__ void mma_f16(float* d, const u32* a, const u32* b) {
    asm volatile(
        "mma.sync.aligned.m16n8k16.row.col.f32.f16.f16.f32 "
        "{%0,%1,%2,%3}, {%4,%5,%6,%7}, {%8,%9}, {%0,%1,%2,%3};"
        : "+f"(d[0]), "+f"(d[1]), "+f"(d[2]), "+f"(d[3])
        : "r"(a[0]), "r"(a[1]), "r"(a[2]), "r"(a[3]), "r"(b[0]), "r"(b[1]));
}

// 3-way fp16 split: x = h1 + h2/2048 + h3/2048 (h2,h3 stored pre-scaled)
static __device__ __forceinline__ void split3(float x, __half& h1, __half& h2,
                                              __half& h3)
{
    h1 = __float2half_rn(x);
    float r1 = x - __half2float(h1);
    h2 = __float2half_rn(r1 * 2048.f);
    float r2 = r1 - __half2float(h2) * (1.f / 2048.f);
    h3 = __float2half_rn(r2 * 2048.f);
}

// ============================================================================
// Generic fp16x6 (fp32-grade) NT GEMM tile: C = alpha * A @ B^T (+bias).
// CTA tile 128x64, BK=32, 8 warps 2(m)x4(n), warp tile 64x16 (NFR=2).
// P0 = A1B1 ; P1 = A1B2s + A2sB1 + A1B3s + A3sB1 + A2s(B2s/s); C = P0 + P1/s.
// MODE 0: row-major C (ldc); MODE 1: head-scatter [b,h,s,d] + bias.
// ============================================================================
template<int MODE>
__device__ void f16x6_tile(const float* __restrict__ A,
                           const float* __restrict__ B,
                           float* __restrict__ C,
                           const float* __restrict__ bias,
                           int K, int lda, int ldb, int ldc,
                           float alpha, int m0, int n0, char* smem_raw)
{
    typedef __half (*H40)[40];
    H40 A1 = (H40)(smem_raw);
    H40 A2 = (H40)(smem_raw + 10240);
    H40 A3 = (H40)(smem_raw + 20480);
    H40 B1 = (H40)(smem_raw + 30720);
    H40 B2 = (H40)(smem_raw + 35840);
    H40 B3 = (H40)(smem_raw + 40960);

    const int tid  = threadIdx.x;
    const int wid  = tid >> 5;
    const int lane = tid & 31;
    const int wm   = wid & 1;
    const int wn   = wid >> 1;       // 0..3
    const int qid  = lane >> 2;
    const int rid  = lane & 3;

    float acc0[4][2][4], acc1[4][2][4];
#pragma unroll
    for (int i = 0; i < 4; i++)
#pragma unroll
        for (int j = 0; j < 2; j++)
#pragma unroll
            for (int t = 0; t < 4; t++) { acc0[i][j][t] = 0.f; acc1[i][j][t] = 0.f; }

    const __half2 inv_s2 = __float2half2_rn(1.f / 2048.f);
    const int nc = K >> 5;

    for (int c = 0; c < nc; c++) {
        const int k0 = c << 5;
        float4 va[4], vb[2];
#pragma unroll
        for (int i = 0; i < 4; i++) {
            int idx = tid + i * 256;              // 0..1023
            int r = idx >> 3, cc = (idx & 7) << 2;
            va[i] = *(const float4*)(A + (size_t)(m0 + r) * lda + k0 + cc);
        }
#pragma unroll
        for (int i = 0; i < 2; i++) {
            int idx = tid + i * 256;              // 0..511
            int r = idx >> 3, cc = (idx & 7) << 2;
            vb[i] = *(const float4*)(B + (size_t)(n0 + r) * ldb + k0 + cc);
        }
        __syncthreads();
#pragma unroll
        for (int i = 0; i < 4; i++) {
            int idx = tid + i * 256;
            int r = idx >> 3, cc = (idx & 7) << 2;
            float xs[4] = {va[i].x, va[i].y, va[i].z, va[i].w};
#pragma unroll
            for (int t = 0; t < 4; t++)
                split3(xs[t], A1[r][cc + t], A2[r][cc + t], A3[r][cc + t]);
        }
#pragma unroll
        for (int i = 0; i < 2; i++) {
            int idx = tid + i * 256;
            int r = idx >> 3, cc = (idx & 7) << 2;
            float xs[4] = {vb[i].x, vb[i].y, vb[i].z, vb[i].w};
#pragma unroll
            for (int t = 0; t < 4; t++)
                split3(xs[t], B1[r][cc + t], B2[r][cc + t], B3[r][cc + t]);
        }
        __syncthreads();

#pragma unroll
        for (int kk = 0; kk < 32; kk += 16) {
            u32 a1[4][4], a2[4][4], a3[4][4];
#pragma unroll
            for (int mt = 0; mt < 4; mt++) {
                int row = wm * 64 + mt * 16 + qid;
                a1[mt][0] = *(const u32*)&A1[row    ][kk + rid * 2];
                a1[mt][1] = *(const u32*)&A1[row + 8][kk + rid * 2];
                a1[mt][2] = *(const u32*)&A1[row    ][kk + rid * 2 + 8];
                a1[mt][3] = *(const u32*)&A1[row + 8][kk + rid * 2 + 8];
                a2[mt][0] = *(const u32*)&A2[row    ][kk + rid * 2];
                a2[mt][1] = *(const u32*)&A2[row + 8][kk + rid * 2];
                a2[mt][2] = *(const u32*)&A2[row    ][kk + rid * 2 + 8];
                a2[mt][3] = *(const u32*)&A2[row + 8][kk + rid * 2 + 8];
                a3[mt][0] = *(const u32*)&A3[row    ][kk + rid * 2];
                a3[mt][1] = *(const u32*)&A3[row + 8][kk + rid * 2];
                a3[mt][2] = *(const u32*)&A3[row    ][kk + rid * 2 + 8];
                a3[mt][3] = *(const u32*)&A3[row + 8][kk + rid * 2 + 8];
            }
            u32 b1[2][2], b2[2][2], b3[2][2], b2r[2][2];
#pragma unroll
            for (int nt = 0; nt < 2; nt++) {
                int col = wn * 16 + nt * 8 + qid;
                b1[nt][0] = *(const u32*)&B1[col][kk + rid * 2];
                b1[nt][1] = *(const u32*)&B1[col][kk + rid * 2 + 8];
                b2[nt][0] = *(const u32*)&B2[col][kk + rid * 2];
                b2[nt][1] = *(const u32*)&B2[col][kk + rid * 2 + 8];
                b3[nt][0] = *(const u32*)&B3[col][kk + rid * 2];
                b3[nt][1] = *(const u32*)&B3[col][kk + rid * 2 + 8];
                __half2 t0 = __hmul2(*(__half2*)&b2[nt][0], inv_s2);
                __half2 t1 = __hmul2(*(__half2*)&b2[nt][1], inv_s2);
                b2r[nt][0] = *(u32*)&t0;
                b2r[nt][1] = *(u32*)&t1;
            }
#pragma unroll
            for (int mt = 0; mt < 4; mt++)
#pragma unroll
                for (int nt = 0; nt < 2; nt++) {
                    mma_f16(acc0[mt][nt], a1[mt], b1[nt]);
                    mma_f16(acc1[mt][nt], a1[mt], b2[nt]);
                    mma_f16(acc1[mt][nt], a2[mt], b1[nt]);
                    mma_f16(acc1[mt][nt], a1[mt], b3[nt]);
                    mma_f16(acc1[mt][nt], a3[mt], b1[nt]);
                    mma_f16(acc1[mt][nt], a2[mt], b2r[nt]);
                }
        }
        __syncthreads();
    }

    const float S = 1.f / 2048.f;
#pragma unroll
    for (int mt = 0; mt < 4; mt++) {
        int r0 = m0 + wm * 64 + mt * 16 + qid;
        int r1 = r0 + 8;
#pragma unroll
        for (int nt = 0; nt < 2; nt++) {
            int cb = n0 + wn * 16 + nt * 8 + rid * 2;
            float v0 = (acc0[mt][nt][0] + acc1[mt][nt][0] * S) * alpha;
            float v1 = (acc0[mt][nt][1] + acc1[mt][nt][1] * S) * alpha;
            float v2 = (acc0[mt][nt][2] + acc1[mt][nt][2] * S) * alpha;
            float v3 = (acc0[mt][nt][3] + acc1[mt][nt][3] * S) * alpha;
            if (MODE == 0) {
                *(float2*)(C + (size_t)r0 * ldc + cb) = make_float2(v0, v1);
                *(float2*)(C + (size_t)r1 * ldc + cb) = make_float2(v2, v3);
            } else {
                float b0 = bias[cb], b1 = bias[cb + 1];
                v0 += b0; v1 += b1; v2 += b0; v3 += b1;
                int h = cb >> 6, d = cb & 63;
                int b0i = r0 >> 11, s0i = r0 & (SS - 1);
                int b1i = r1 >> 11, s1i = r1 & (SS - 1);
                *(float2*)(C + (((size_t)(b0i * HH + h)) * SS + s0i) * DK + d) =
                    make_float2(v0, v1);
                *(float2*)(C + (((size_t)(b1i * HH + h)) * SS + s1i) * DK + d) =
                    make_float2(v2, v3);
            }
        }
    }
}

// ============================================================================
// fp16x3 split GEMM body (V projection): 22-bit accurate.
// ============================================================================
__device__ void hgemm3_body(const float* __restrict__ Ag,
                            const float* __restrict__ Bg,
                            float* __restrict__ Cg,
                            const float* __restrict__ bias,
                            int m0, int n0, char* smem_raw)
{
    typedef __half (*HArr)[40];
    HArr Ah = (HArr)(smem_raw);
    HArr Al = (HArr)(smem_raw + 10240);
    HArr Bh = (HArr)(smem_raw + 20480);
    HArr Bl = (HArr)(smem_raw + 30720);

    const int tid  = threadIdx.x;
    const int wid  = tid >> 5;
    const int lane = tid & 31;
    const int wm   = wid & 1;
    const int wn   = wid >> 1;
    const int qid  = lane >> 2;
    const int rid  = lane & 3;

    float acc[4][4][4];
#pragma unroll
    for (int i = 0; i < 4; i++)
#pragma unroll
        for (int j = 0; j < 4; j++)
#pragma unroll
            for (int t = 0; t < 4; t++) acc[i][j][t] = 0.f;

    for (int c = 0; c < DD / 32; c++) {
        const int k0 = c << 5;
        float4 va[4], vb[4];
#pragma unroll
        for (int i = 0; i < 4; i++) {
            int idx = tid + i * 256;
            int r = idx >> 3, cc = (idx & 7) << 2;
            va[i] = *(const float4*)(Ag + (size_t)(m0 + r) * DD + k0 + cc);
            vb[i] = *(const float4*)(Bg + (size_t)(n0 + r) * DD + k0 + cc);
        }
        __syncthreads();
#pragma unroll
        for (int i = 0; i < 4; i++) {
            int idx = tid + i * 256;
            int r = idx >> 3, cc = (idx & 7) << 2;
            float xa[4] = {va[i].x, va[i].y, va[i].z, va[i].w};
            float xb[4] = {vb[i].x, vb[i].y, vb[i].z, vb[i].w};
#pragma unroll
            for (int t = 0; t < 4; t++) {
                __half h = __float2half_rn(xa[t]);
                Ah[r][cc + t] = h;
                Al[r][cc + t] = __float2half_rn(xa[t] - __half2float(h));
                __half g = __float2half_rn(xb[t]);
                Bh[r][cc + t] = g;
                Bl[r][cc + t] = __float2half_rn(xb[t] - __half2float(g));
            }
        }
        __syncthreads();

#pragma unroll
        for (int kk = 0; kk < 32; kk += 16) {
            u32 ah[4][4], al[4][4], bh[4][2], bl[4][2];
#pragma unroll
            for (int mt = 0; mt < 4; mt++) {
                int row = wm * 64 + mt * 16 + qid;
                ah[mt][0] = *(const u32*)&Ah[row    ][kk + rid * 2];
                ah[mt][1] = *(const u32*)&Ah[row + 8][kk + rid * 2];
                ah[mt][2] = *(const u32*)&Ah[row    ][kk + rid * 2 + 8];
                ah[mt][3] = *(const u32*)&Ah[row + 8][kk + rid * 2 + 8];
                al[mt][0] = *(const u32*)&Al[row    ][kk + rid * 2];
                al[mt][1] = *(const u32*)&Al[row + 8][kk + rid * 2];
                al[mt][2] = *(const u32*)&Al[row    ][kk + rid * 2 + 8];
                al[mt][3] = *(const u32*)&Al[row + 8][kk + rid * 2 + 8];
            }
#pragma unroll
            for (int nt = 0; nt < 4; nt++) {
                int col = wn * 32 + nt * 8 + qid;
                bh[nt][0] = *(const u32*)&Bh[col][kk + rid * 2];
                bh[nt][1] = *(const u32*)&Bh[col][kk + rid * 2 + 8];
                bl[nt][0] = *(const u32*)&Bl[col][kk + rid * 2];
                bl[nt][1] = *(const u32*)&Bl[col][kk + rid * 2 + 8];
            }
#pragma unroll
            for (int mt = 0; mt < 4; mt++)
#pragma unroll
                for (int nt = 0; nt < 4; nt++) {
                    mma_f16(acc[mt][nt], ah[mt], bh[nt]);
                    mma_f16(acc[mt][nt], ah[mt], bl[nt]);
                    mma_f16(acc[mt][nt], al[mt], bh[nt]);
                }
        }
        __syncthreads();
    }

#pragma unroll
    for (int mt = 0; mt < 4; mt++) {
        int r0 = m0 + wm * 64 + mt * 16 + qid;
        int r1 = r0 + 8;
#pragma unroll
        for (int nt = 0; nt < 4; nt++) {
            int cb = n0 + wn * 32 + nt * 8 + rid * 2;
            float b0 = bias[cb], b1 = bias[cb + 1];
            float v0 = acc[mt][nt][0] + b0;
            float v1 = acc[mt][nt][1] + b1;
            float v2 = acc[mt][nt][2] + b0;
            float v3 = acc[mt][nt][3] + b1;
            int h = cb >> 6, d = cb & 63;
            int b0i = r0 >> 11, s0i = r0 & (SS - 1);
            int b1i = r1 >> 11, s1i = r1 & (SS - 1);
            *(float2*)(Cg + (((size_t)(b0i * HH + h)) * SS + s0i) * DK + d) =
                make_float2(v0, v1);
            *(float2*)(Cg + (((size_t)(b1i * HH + h)) * SS + s1i) * DK + d) =
                make_float2(v2, v3);
        }
    }
}

// ============================================================================
// QK projections, pipe-mixed: x<4 -> FFMA (cols 0..511), x>=4 -> fp16x6
// (cols 512..1023). z selects Q / K. Types interleave along x => every
// scheduling window contains both pipe classes.
// ============================================================================
__global__ __launch_bounds__(256, 2)
void qk_mixed(const float* __restrict__ q,  const float* __restrict__ Wq,
              const float* __restrict__ bq, float* __restrict__ qh,
              const float* __restrict__ k,  const float* __restrict__ Wk,
              const float* __restrict__ bk, float* __restrict__ kh)
{
    __shared__ __align__(16) char smem_raw[46080];
    const float* A  = blockIdx.z ? k  : q;
    const float* B  = blockIdx.z ? Wk : Wq;
    const float* bi = blockIdx.z ? bk : bq;
    float*       C  = blockIdx.z ? kh : qh;
    const int m0 = blockIdx.y * 128;

    if (blockIdx.x < 4) {
        float (*As)[8][128] = (float(*)[8][128])(smem_raw);
        float (*Bs)[8][128] = (float(*)[8][128])(smem_raw + 8192);
        ffma_tile<1>(A, B, C, bi, DD, DD, DD, 0, 1.f,
                     m0, blockIdx.x * 128, As, Bs);
    } else {
        f16x6_tile<1>(A, B, C, bi, DD, DD, DD, 0, 1.f,
                      m0, 512 + (blockIdx.x - 4) * 64, smem_raw);
    }
}

// ============================================================================
// Scores, pipe-mixed (+ V projection): z<32: bh=z; x<8 -> FFMA scores
// (cols 0..1023), x in [8,24) -> fp16x6 scores (cols 1024..2047).
// z==32: V projection (fp16x3), flat-indexed.
// ============================================================================
__global__ __launch_bounds__(256, 2)
void scores_vproj_mixed(const float* __restrict__ qh, const float* __restrict__ kh,
                        float* __restrict__ probs,
                        const float* __restrict__ v, const float* __restrict__ Wv,
                        const float* __restrict__ bv, float* __restrict__ vh)
{
    __shared__ __align__(16) char smem_raw[46080];

    if (blockIdx.z < 32) {
        const size_t z = blockIdx.z;
        const float* A = qh + z * SS * DK;
        const float* B = kh + z * SS * DK;
        float* C = probs + z * SS * SS;
        const int m0 = blockIdx.y * 128;
        if (blockIdx.x < 8) {
            float (*As)[8][128] = (float(*)[8][128])(smem_raw);
            float (*Bs)[8][128] = (float(*)[8][128])(smem_raw + 8192);
            ffma_tile<0>(A, B, C, nullptr, DK, DK, DK, SS, 0.125f,
                         m0, blockIdx.x * 128, As, Bs);
        } else {
            f16x6_tile<0>(A, B, C, nullptr, DK, DK, DK, SS, 0.125f,
                          m0, 1024 + (blockIdx.x - 8) * 64, smem_raw);
        }
    } else {
        int flat = blockIdx.y * 24 + blockIdx.x;   // 0..383
        if (flat >= 256) return;
        int m0 = (flat >> 3) * 128;
        int n0 = (flat & 7) * 128;
        hgemm3_body(v, Wv, vh, bv, m0, n0, smem_raw);
    }
}

// ============================================================================
// fp16 m16n8k16 NT GEMM (value path). A fp16, B fp16 or fp32(cvt), f32 acc.
// mode 3: AV -> fp16 concat scatter (z=(b,h)); mode 0: fp32 C + bias.
// ============================================================================
template<int NT, bool B_F32>
__global__ __launch_bounds__(256)
void hgemm_nt(const __half* __restrict__ Ag, const void* __restrict__ Bv,
              float* __restrict__ Cf, __half* __restrict__ Ch,
              const float* __restrict__ bias,
              int K, int lda, int ldb, int ldc,
              long long sA, long long sB,
              int mode)
{
    __shared__ __half As[128][56];
    __shared__ __half Bs[NT][56];

    const int tid  = threadIdx.x;
    const int wid  = tid >> 5;
    const int lane = tid & 31;
    const int wm   = wid & 1;
    const int wn   = wid >> 1;
    const int qid  = lane >> 2;
    const int rid  = lane & 3;

    constexpr int WN  = NT / 4;      // 32 or 16
    constexpr int NFR = WN / 8;      // 4 or 2

    const __half* A = Ag + (size_t)blockIdx.z * sA;
    const int m0 = blockIdx.y * 128;
    const int n0 = blockIdx.x * NT;

    float acc[4][NFR][4];
#pragma unroll
    for (int i = 0; i < 4; i++)
#pragma unroll
        for (int j = 0; j < NFR; j++)
#pragma unroll
            for (int t = 0; t < 4; t++) acc[i][j][t] = 0.f;

    const int nc = K >> 5;
    for (int c = 0; c < nc; c++) {
        const int k0 = c << 5;
        uint4 va[2];
#pragma unroll
        for (int i = 0; i < 2; i++) {
            int idx = tid + i * 256;
            int r = idx >> 2, seg = (idx & 3) << 3;
            va[i] = *(const uint4*)(A + (size_t)(m0 + r) * lda + k0 + seg);
        }
        if (B_F32) {
            const float* B = (const float*)Bv + (size_t)blockIdx.z * sB;
            constexpr int BI = (NT * 32) / (4 * 256);
            float4 vb[BI];
#pragma unroll
            for (int i = 0; i < BI; i++) {
                int idx = tid + i * 256;
                int r = idx >> 3, seg = (idx & 7) << 2;
                vb[i] = *(const float4*)(B + (size_t)(n0 + r) * ldb + k0 + seg);
            }
            __syncthreads();
#pragma unroll
            for (int i = 0; i < 2; i++) {
                int idx = tid + i * 256;
                int r = idx >> 2, seg = (idx & 3) << 3;
                *(uint4*)&As[r][seg] = va[i];
            }
#pragma unroll
            for (int i = 0; i < BI; i++) {
                int idx = tid + i * 256;
                int r = idx >> 3, seg = (idx & 7) << 2;
                *(__half2*)&Bs[r][seg]     = __floats2half2_rn(vb[i].x, vb[i].y);
                *(__half2*)&Bs[r][seg + 2] = __floats2half2_rn(vb[i].z, vb[i].w);
            }
        } else {
            const __half* B = (const __half*)Bv + (size_t)blockIdx.z * sB;
            constexpr int BI = (NT * 32) / (8 * 256) > 0 ? (NT * 32) / (8 * 256) : 1;
            uint4 vb[BI];
#pragma unroll
            for (int i = 0; i < BI; i++) {
                int idx = tid + i * 256;
                int r = idx >> 2, seg = (idx & 3) << 3;
                vb[i] = *(const uint4*)(B + (size_t)(n0 + r) * ldb + k0 + seg);
            }
            __syncthreads();
#pragma unroll
            for (int i = 0; i < 2; i++) {
                int idx = tid + i * 256;
                int r = idx >> 2, seg = (idx & 3) << 3;
                *(uint4*)&As[r][seg] = va[i];
            }
#pragma unroll
            for (int i = 0; i < BI; i++) {
                int idx = tid + i * 256;
                int r = idx >> 2, seg = (idx & 3) << 3;
                *(uint4*)&Bs[r][seg] = vb[i];
            }
        }
        __syncthreads();

#pragma unroll
        for (int kk = 0; kk < 32; kk += 16) {
            u32 af[4][4], bf[NFR][2];
#pragma unroll
            for (int mt = 0; mt < 4; mt++) {
                int row = wm * 64 + mt * 16 + qid;
                af[mt][0] = *(const u32*)&As[row    ][kk + rid * 2];
                af[mt][1] = *(const u32*)&As[row + 8][kk + rid * 2];
                af[mt][2] = *(const u32*)&As[row    ][kk + rid * 2 + 8];
                af[mt][3] = *(const u32*)&As[row + 8][kk + rid * 2 + 8];
            }
#pragma unroll
            for (int nt = 0; nt < NFR; nt++) {
                int col = wn * WN + nt * 8 + qid;
                bf[nt][0] = *(const u32*)&Bs[col][kk + rid * 2];
                bf[nt][1] = *(const u32*)&Bs[col][kk + rid * 2 + 8];
            }
#pragma unroll
            for (int mt = 0; mt < 4; mt++)
#pragma unroll
                for (int nt = 0; nt < NFR; nt++)
                    mma_f16(acc[mt][nt], af[mt], bf[nt]);
        }
        __syncthreads();
    }

#pragma unroll
    for (int mt = 0; mt < 4; mt++) {
        int r0 = m0 + wm * 64 + mt * 16 + qid;
        int r1 = r0 + 8;
#pragma unroll
        for (int nt = 0; nt < NFR; nt++) {
            int cb = n0 + wn * WN + nt * 8 + rid * 2;
            float v0 = acc[mt][nt][0];
            float v1 = acc[mt][nt][1];
            float v2 = acc[mt][nt][2];
            float v3 = acc[mt][nt][3];
            if (mode == 0) {
                float b0 = bias[cb], b1 = bias[cb + 1];
                *(float2*)(Cf + (size_t)r0 * ldc + cb) = make_float2(v0 + b0, v1 + b1);
                *(float2*)(Cf + (size_t)r1 * ldc + cb) = make_float2(v2 + b0, v3 + b1);
            } else {
                int z = blockIdx.z, b = z >> 4, h = z & 15;
                *(__half2*)(Ch + ((size_t)b * SS + r0) * DD + h * DK + cb) =
                    __floats2half2_rn(v0, v1);
                *(__half2*)(Ch + ((size_t)b * SS + r1) * DD + h * DK + cb) =
                    __floats2half2_rn(v2, v3);
            }
        }
    }
}

// ============================================================================
// Fused softmax + colsum partials; fp16 probs out. Two rows per iteration.
// ============================================================================
__global__ __launch_bounds__(256)
void softmax_colsum_kernel(const float* __restrict__ scores,
                           __half* __restrict__ probsh,
                           float* __restrict__ part)
{
    __shared__ float redA[2][8];
    __shared__ float redB[2][8];
    const int rb = blockIdx.x;   // 0..31
    const int bh = blockIdx.y;
    const int tid = threadIdx.x;
    const int wid = tid >> 5, lane = tid & 31;

    float cs[8];
#pragma unroll
    for (int i = 0; i < 8; i++) cs[i] = 0.f;

    for (int r = 0; r < 64; r += 2) {
        const float* row0 = scores + ((size_t)bh * SS + rb * 64 + r) * SS + tid * 8;
        const float* row1 = row0 + SS;
        float x0[8], x1[8];
        *(float4*)(x0)     = *(const float4*)(row0);
        *(float4*)(x0 + 4) = *(const float4*)(row0 + 4);
        *(float4*)(x1)     = *(const float4*)(row1);
        *(float4*)(x1 + 4) = *(const float4*)(row1 + 4);

        float m0 = x0[0], m1 = x1[0];
#pragma unroll
        for (int i = 1; i < 8; i++) { m0 = fmaxf(m0, x0[i]); m1 = fmaxf(m1, x1[i]); }
#pragma unroll
        for (int o = 16; o > 0; o >>= 1) {
            m0 = fmaxf(m0, __shfl_xor_sync(0xFFFFFFFF, m0, o));
            m1 = fmaxf(m1, __shfl_xor_sync(0xFFFFFFFF, m1, o));
        }
        if (lane == 0) { redA[0][wid] = m0; redA[1][wid] = m1; }
        __syncthreads();
        m0 = redA[0][0]; m1 = redA[1][0];
#pragma unroll
        for (int w = 1; w < 8; w++) {
            m0 = fmaxf(m0, redA[0][w]);
            m1 = fmaxf(m1, redA[1][w]);
        }

        float s0 = 0.f, s1 = 0.f;
#pragma unroll
        for (int i = 0; i < 8; i++) {
            x0[i] = __expf(x0[i] - m0); s0 += x0[i];
            x1[i] = __expf(x1[i] - m1); s1 += x1[i];
        }
#pragma unroll
        for (int o = 16; o > 0; o >>= 1) {
            s0 += __shfl_xor_sync(0xFFFFFFFF, s0, o);
            s1 += __shfl_xor_sync(0xFFFFFFFF, s1, o);
        }
        if (lane == 0) { redB[0][wid] = s0; redB[1][wid] = s1; }
        __syncthreads();
        s0 = redB[0][0]; s1 = redB[1][0];
#pragma unroll
        for (int w = 1; w < 8; w++) { s0 += redB[0][w]; s1 += redB[1][w]; }
        float inv0 = 1.0f / s0;
        float inv1 = 1.0f / s1;

        __half2 h0[4], h1[4];
#pragma unroll
        for (int i = 0; i < 8; i += 2) {
            float p0 = x0[i] * inv0, p1 = x0[i + 1] * inv0;
            cs[i] += p0; cs[i + 1] += p1;
            h0[i >> 1] = __floats2half2_rn(p0, p1);
        }
#pragma unroll
        for (int i = 0; i < 8; i += 2) {
            float p0 = x1[i] * inv1, p1 = x1[i + 1] * inv1;
            cs[i] += p0; cs[i + 1] += p1;
            h1[i >> 1] = __floats2half2_rn(p0, p1);
        }
        *(uint4*)(probsh + ((size_t)bh * SS + rb * 64 + r) * SS + tid * 8) =
            *(uint4*)h0;
        *(uint4*)(probsh + ((size_t)bh * SS + rb * 64 + r + 1) * SS + tid * 8) =
            *(uint4*)h1;
        __syncthreads();
    }
#pragma unroll
    for (int i = 0; i < 8; i++)
        part[((size_t)bh * 32 + rb) * SS + tid * 8 + i] = cs[i];
}

// ============================================================================
// Fused colsum-reduce + top-k mask (bitonic sort). One block per (b,h).
// ============================================================================
__global__ void topk_mask_kernel(const float* __restrict__ part,
                                 float* __restrict__ mask)
{
    __shared__ float s[SS];
    __shared__ float cs_sh[SS];
    const int bh = blockIdx.x;
    const int tid = threadIdx.x; // 1024

    for (int j = tid; j < SS; j += 1024) {
        float sum = 0.f;
#pragma unroll
        for (int rb = 0; rb < 32; rb++)
            sum += part[((size_t)bh * 32 + rb) * SS + j];
        s[j] = sum;
        cs_sh[j] = sum;
    }
    __syncthreads();

    for (int ksz = 2; ksz <= SS; ksz <<= 1) {
        for (int j = ksz >> 1; j > 0; j >>= 1) {
            for (int i = tid; i < SS; i += 1024) {
                int p = i ^ j;
                if (p > i) {
                    bool up = ((i & ksz) == 0);
                    float a = s[i], b = s[p];
                    if ((a > b) == up) { s[i] = b; s[p] = a; }
                }
            }
            __syncthreads();
        }
    }
    float thr = s[SS - KEEP];
    mask[bh * SS + tid]        = (cs_sh[tid]        >= thr) ? 1.f : 0.f;
    mask[bh * SS + tid + 1024] = (cs_sh[tid + 1024] >= thr) ? 1.f : 0.f;
}

// ============================================================================
// Masked transpose to fp16: vtmh[bh][d][s] = fp16(vh[bh][s][d] * mask[bh][s])
// ============================================================================
__global__ void vt_mask_kernel(const float* __restrict__ vh,
                               const float* __restrict__ mask,
                               __half* __restrict__ vtmh)
{
    __shared__ float t[32][33];
    const int bh = blockIdx.z;
    const int s0 = blockIdx.x * 32;
    const int d0 = blockIdx.y * 32;
    const int lx = threadIdx.x & 31;
    const int ly = threadIdx.x >> 5;
    for (int i = ly; i < 32; i += 8)
        t[i][lx] = vh[((size_t)bh * SS + s0 + i) * DK + d0 + lx] * mask[bh * SS + s0 + i];
    __syncthreads();
    for (int i = ly; i < 32; i += 8)
        vtmh[((size_t)bh * DK + d0 + i) * SS + s0 + lx] = __float2half_rn(t[lx][i]);
}

// ---------------------------------------------------------------------------
extern "C" void kernel_launch(void* const* d_in, const int* in_sizes, int n_in,
                              void* d_out, int out_size)
{
    (void)in_sizes; (void)n_in; (void)out_size;
    const float* q  = (const float*)d_in[0];
    const float* k  = (const float*)d_in[1];
    const float* v  = (const float*)d_in[2];
    const float* Wq = (const float*)d_in[3];
    const float* bq = (const float*)d_in[4];
    const float* Wk = (const float*)d_in[5];
    const float* bk = (const float*)d_in[6];
    const float* Wv = (const float*)d_in[7];
    const float* bv = (const float*)d_in[8];
    const float* Wo = (const float*)d_in[9];
    const float* bo = (const float*)d_in[10];
    float* out = (float*)d_out;

    float *qh, *kh, *vh, *probs, *part, *mask;
    __half *vtmh, *probsh, *concath;
    cudaGetSymbolAddress((void**)&qh,      g_qh);
    cudaGetSymbolAddress((void**)&kh,      g_kh);
    cudaGetSymbolAddress((void**)&vh,      g_vh);
    cudaGetSymbolAddress((void**)&vtmh,    g_vtmh);
    cudaGetSymbolAddress((void**)&probs,   g_probs);
    cudaGetSymbolAddress((void**)&probsh,  g_probsh);
    cudaGetSymbolAddress((void**)&part,    g_part);
    cudaGetSymbolAddress((void**)&mask,    g_mask);
    cudaGetSymbolAddress((void**)&concath, g_concath);

    // Q + K projections, FFMA/HMMA pipe-mixed along x
    dim3 gqk(12, (BB * SS) / 128, 2);
    qk_mixed<<<gqk, 256>>>(q, Wq, bq, qh, k, Wk, bk, kh);

    // Scores (pipe-mixed along x) + V projection (z==32)
    dim3 gsv(24, SS / 128, BHN + 1);
    scores_vproj_mixed<<<gsv, 256>>>(qh, kh, probs, v, Wv, bv, vh);

    // Fused softmax + colsum partials (fp16 probs out)
    softmax_colsum_kernel<<<dim3(32, BHN), 256>>>(probs, probsh, part);

    // Fused colsum reduce + top-k mask
    topk_mask_kernel<<<BHN, 1024>>>(part, mask);

    // Masked V transpose -> fp16 vtmh[bh][d][s]
    vt_mask_kernel<<<dim3(SS / 32, DK / 32, BHN), 256>>>(vh, mask, vtmh);

    // AV (fp16 mma): per (b,h) 2048x64x2048 -> fp16 concat
    dim3 gav(1, SS / 128, BHN);
    hgemm_nt<64, false><<<gav, 256>>>(probsh, vtmh, nullptr, concath, nullptr,
                                      SS, SS, SS, 0,
                                      (long long)SS * SS, (long long)DK * SS, 3);

    // Output projection (fp16 mma, Wo cvt on load): fp32 out + bias
    dim3 gop(DD / 128, (BB * SS) / 128, 1);
    hgemm_nt<128, true><<<gop, 256>>>(concath, Wo, out, nullptr, bo,
                                      DD, DD, DD, DD, 0, 0, 0);
}

// round 13
// speedup vs baseline: 1.0503x; 1.0013x over previous
#include <cuda_runtime.h>
#include <cuda_fp16.h>
#include <math.h>

// Problem constants
#define BB   2
#define HH   16
#define SS   2048
#define DD   1024
#define DK   64
#define BHN  (BB*HH)      // 32
#define KEEP 1843         // int(2048*0.9)

typedef unsigned int u32;

// ---------------- scratch (device globals; no cudaMalloc allowed) ----------
__device__ float  g_qh[(size_t)BHN * SS * DK];      // [b,h,s,d]
__device__ float  g_kh[(size_t)BHN * SS * DK];
__device__ float  g_vh[(size_t)BHN * SS * DK];
__device__ __half g_vtmh[(size_t)BHN * DK * SS];    // masked V^T fp16 [b,h,d,s]
__device__ float  g_probs[(size_t)BHN * SS * SS];   // 512 MiB fp32 scores
__device__ __half g_probsh[(size_t)BHN * SS * SS];  // 256 MiB fp16 probs
__device__ float  g_part[(size_t)BHN * 32 * SS];    // colsum partials
__device__ float  g_mask[BHN * SS];
__device__ __half g_concath[(size_t)BB * SS * DD];  // fp16 concat [b,s,h*64+d]

// ============================================================================
// FFMA fp32 NT GEMM body, double-buffered smem; m0/n0 passed in.
// Accumulation order identical to R1..R12 => bitwise-same results.
// MODE 0: row-major C (ldc); MODE 1: head-scatter [b,h,s,d].
// ============================================================================
template<int MODE>
__device__ __forceinline__ void ffma_tile(
    const float* __restrict__ A, const float* __restrict__ B,
    float* __restrict__ C, const float* __restrict__ bias,
    int K, int lda, int ldb, int ldc, float alpha, int m0, int n0,
    float As[2][8][128], float Bs[2][8][128])
{
    const int tid = threadIdx.x;
    const int tx = tid & 15;
    const int ty = tid >> 4;
    const int lrow = tid >> 1;
    const int lcol = (tid & 1) * 4;

    float acc[8][8];
#pragma unroll
    for (int i = 0; i < 8; i++)
#pragma unroll
        for (int j = 0; j < 8; j++) acc[i][j] = 0.f;

    const float* Aptr = A + (size_t)(m0 + lrow) * lda + lcol;
    const float* Bptr = B + (size_t)(n0 + lrow) * ldb + lcol;

    {
        float4 av = *(const float4*)(Aptr);
        float4 bv = *(const float4*)(Bptr);
        As[0][lcol + 0][lrow] = av.x; As[0][lcol + 1][lrow] = av.y;
        As[0][lcol + 2][lrow] = av.z; As[0][lcol + 3][lrow] = av.w;
        Bs[0][lcol + 0][lrow] = bv.x; Bs[0][lcol + 1][lrow] = bv.y;
        Bs[0][lcol + 2][lrow] = bv.z; Bs[0][lcol + 3][lrow] = bv.w;
    }
    __syncthreads();

    int buf = 0;
    for (int k0 = 8; k0 < K; k0 += 8) {
        float4 av = *(const float4*)(Aptr + k0);
        float4 bv = *(const float4*)(Bptr + k0);
        const int nb = buf ^ 1;
        As[nb][lcol + 0][lrow] = av.x; As[nb][lcol + 1][lrow] = av.y;
        As[nb][lcol + 2][lrow] = av.z; As[nb][lcol + 3][lrow] = av.w;
        Bs[nb][lcol + 0][lrow] = bv.x; Bs[nb][lcol + 1][lrow] = bv.y;
        Bs[nb][lcol + 2][lrow] = bv.z; Bs[nb][lcol + 3][lrow] = bv.w;
#pragma unroll
        for (int kk = 0; kk < 8; kk++) {
            float a[8], b[8];
            *(float4*)(a)     = *(const float4*)&As[buf][kk][ty * 8];
            *(float4*)(a + 4) = *(const float4*)&As[buf][kk][ty * 8 + 4];
            *(float4*)(b)     = *(const float4*)&Bs[buf][kk][tx * 8];
            *(float4*)(b + 4) = *(const float4*)&Bs[buf][kk][tx * 8 + 4];
#pragma unroll
            for (int i = 0; i < 8; i++)
#pragma unroll
                for (int j = 0; j < 8; j++) acc[i][j] += a[i] * b[j];
        }
        __syncthreads();
        buf = nb;
    }
#pragma unroll
    for (int kk = 0; kk < 8; kk++) {
        float a[8], b[8];
        *(float4*)(a)     = *(const float4*)&As[buf][kk][ty * 8];
        *(float4*)(a + 4) = *(const float4*)&As[buf][kk][ty * 8 + 4];
        *(float4*)(b)     = *(const float4*)&Bs[buf][kk][tx * 8];
        *(float4*)(b + 4) = *(const float4*)&Bs[buf][kk][tx * 8 + 4];
#pragma unroll
        for (int i = 0; i < 8; i++)
#pragma unroll
            for (int j = 0; j < 8; j++) acc[i][j] += a[i] * b[j];
    }

    if (MODE == 0) {
#pragma unroll
        for (int i = 0; i < 8; i++) {
            int m = m0 + ty * 8 + i;
            float out[8];
#pragma unroll
            for (int j = 0; j < 8; j++) {
                int n = n0 + tx * 8 + j;
                out[j] = acc[i][j] * alpha + (bias ? bias[n] : 0.f);
            }
            float* crow = C + (size_t)m * ldc + n0 + tx * 8;
            *(float4*)(crow)     = *(float4*)(out);
            *(float4*)(crow + 4) = *(float4*)(out + 4);
        }
    } else {
#pragma unroll
        for (int i = 0; i < 8; i++) {
            int m = m0 + ty * 8 + i;
            int b = m >> 11;
            int s = m & (SS - 1);
#pragma unroll
            for (int j = 0; j < 8; j++) {
                int n = n0 + tx * 8 + j;
                int h = n >> 6;
                int d = n & 63;
                C[(((size_t)(b * HH + h)) * SS + s) * DK + d] =
                    acc[i][j] * alpha + (bias ? bias[n] : 0.f);
            }
        }
    }
}

// ============================================================================
// fp16 mma primitive
// ============================================================================
static __device__ __forceinline__ void mma_f16(float* d, const u32* a, const u32* b) {
    asm volatile(
        "mma.sync.aligned.m16n8k16.row.col.f32.f16.f16.f32 "
        "{%0,%1,%2,%3}, {%4,%5,%6,%7}, {%8,%9}, {%0,%1,%2,%3};"
        : "+f"(d[0]), "+f"(d[1]), "+f"(d[2]), "+f"(d[3])
        : "r"(a[0]), "r"(a[1]), "r"(a[2]), "r"(a[3]), "r"(b[0]), "r"(b[1]));
}

// 3-way fp16 split: x = h1 + h2/2048 + h3/2048 (h2,h3 stored pre-scaled)
static __device__ __forceinline__ void split3(float x, __half& h1, __half& h2,
                                              __half& h3)
{
    h1 = __float2half_rn(x);
    float r1 = x - __half2float(h1);
    h2 = __float2half_rn(r1 * 2048.f);
    float r2 = r1 - __half2float(h2) * (1.f / 2048.f);
    h3 = __float2half_rn(r2 * 2048.f);
}

// ============================================================================
// Generic fp16x6 (fp32-grade) NT GEMM tile: C = alpha * A @ B^T (+bias).
// CTA tile 128x64, BK=32, 8 warps 2(m)x4(n), warp tile 64x16 (NFR=2).
// P0 = A1B1 ; P1 = A1B2s + A2sB1 + A1B3s + A3sB1 + A2s(B2s/s); C = P0 + P1/s.
// MODE 0: row-major C (ldc); MODE 1: head-scatter [b,h,s,d] + bias.
// ============================================================================
template<int MODE>
__device__ void f16x6_tile(const float* __restrict__ A,
                           const float* __restrict__ B,
                           float* __restrict__ C,
                           const float* __restrict__ bias,
                           int K, int lda, int ldb, int ldc,
                           float alpha, int m0, int n0, char* smem_raw)
{
    typedef __half (*H40)[40];
    H40 A1 = (H40)(smem_raw);
    H40 A2 = (H40)(smem_raw + 10240);
    H40 A3 = (H40)(smem_raw + 20480);
    H40 B1 = (H40)(smem_raw + 30720);
    H40 B2 = (H40)(smem_raw + 35840);
    H40 B3 = (H40)(smem_raw + 40960);

    const int tid  = threadIdx.x;
    const int wid  = tid >> 5;
    const int lane = tid & 31;
    const int wm   = wid & 1;
    const int wn   = wid >> 1;       // 0..3
    const int qid  = lane >> 2;
    const int rid  = lane & 3;

    float acc0[4][2][4], acc1[4][2][4];
#pragma unroll
    for (int i = 0; i < 4; i++)
#pragma unroll
        for (int j = 0; j < 2; j++)
#pragma unroll
            for (int t = 0; t < 4; t++) { acc0[i][j][t] = 0.f; acc1[i][j][t] = 0.f; }

    const __half2 inv_s2 = __float2half2_rn(1.f / 2048.f);
    const int nc = K >> 5;

    for (int c = 0; c < nc; c++) {
        const int k0 = c << 5;
        float4 va[4], vb[2];
#pragma unroll
        for (int i = 0; i < 4; i++) {
            int idx = tid + i * 256;              // 0..1023
            int r = idx >> 3, cc = (idx & 7) << 2;
            va[i] = *(const float4*)(A + (size_t)(m0 + r) * lda + k0 + cc);
        }
#pragma unroll
        for (int i = 0; i < 2; i++) {
            int idx = tid + i * 256;              // 0..511
            int r = idx >> 3, cc = (idx & 7) << 2;
            vb[i] = *(const float4*)(B + (size_t)(n0 + r) * ldb + k0 + cc);
        }
        __syncthreads();
#pragma unroll
        for (int i = 0; i < 4; i++) {
            int idx = tid + i * 256;
            int r = idx >> 3, cc = (idx & 7) << 2;
            float xs[4] = {va[i].x, va[i].y, va[i].z, va[i].w};
#pragma unroll
            for (int t = 0; t < 4; t++)
                split3(xs[t], A1[r][cc + t], A2[r][cc + t], A3[r][cc + t]);
        }
#pragma unroll
        for (int i = 0; i < 2; i++) {
            int idx = tid + i * 256;
            int r = idx >> 3, cc = (idx & 7) << 2;
            float xs[4] = {vb[i].x, vb[i].y, vb[i].z, vb[i].w};
#pragma unroll
            for (int t = 0; t < 4; t++)
                split3(xs[t], B1[r][cc + t], B2[r][cc + t], B3[r][cc + t]);
        }
        __syncthreads();

#pragma unroll
        for (int kk = 0; kk < 32; kk += 16) {
            u32 a1[4][4], a2[4][4], a3[4][4];
#pragma unroll
            for (int mt = 0; mt < 4; mt++) {
                int row = wm * 64 + mt * 16 + qid;
                a1[mt][0] = *(const u32*)&A1[row    ][kk + rid * 2];
                a1[mt][1] = *(const u32*)&A1[row + 8][kk + rid * 2];
                a1[mt][2] = *(const u32*)&A1[row    ][kk + rid * 2 + 8];
                a1[mt][3] = *(const u32*)&A1[row + 8][kk + rid * 2 + 8];
                a2[mt][0] = *(const u32*)&A2[row    ][kk + rid * 2];
                a2[mt][1] = *(const u32*)&A2[row + 8][kk + rid * 2];
                a2[mt][2] = *(const u32*)&A2[row    ][kk + rid * 2 + 8];
                a2[mt][3] = *(const u32*)&A2[row + 8][kk + rid * 2 + 8];
                a3[mt][0] = *(const u32*)&A3[row    ][kk + rid * 2];
                a3[mt][1] = *(const u32*)&A3[row + 8][kk + rid * 2];
                a3[mt][2] = *(const u32*)&A3[row    ][kk + rid * 2 + 8];
                a3[mt][3] = *(const u32*)&A3[row + 8][kk + rid * 2 + 8];
            }
            u32 b1[2][2], b2[2][2], b3[2][2], b2r[2][2];
#pragma unroll
            for (int nt = 0; nt < 2; nt++) {
                int col = wn * 16 + nt * 8 + qid;
                b1[nt][0] = *(const u32*)&B1[col][kk + rid * 2];
                b1[nt][1] = *(const u32*)&B1[col][kk + rid * 2 + 8];
                b2[nt][0] = *(const u32*)&B2[col][kk + rid * 2];
                b2[nt][1] = *(const u32*)&B2[col][kk + rid * 2 + 8];
                b3[nt][0] = *(const u32*)&B3[col][kk + rid * 2];
                b3[nt][1] = *(const u32*)&B3[col][kk + rid * 2 + 8];
                __half2 t0 = __hmul2(*(__half2*)&b2[nt][0], inv_s2);
                __half2 t1 = __hmul2(*(__half2*)&b2[nt][1], inv_s2);
                b2r[nt][0] = *(u32*)&t0;
                b2r[nt][1] = *(u32*)&t1;
            }
#pragma unroll
            for (int mt = 0; mt < 4; mt++)
#pragma unroll
                for (int nt = 0; nt < 2; nt++) {
                    mma_f16(acc0[mt][nt], a1[mt], b1[nt]);
                    mma_f16(acc1[mt][nt], a1[mt], b2[nt]);
                    mma_f16(acc1[mt][nt], a2[mt], b1[nt]);
                    mma_f16(acc1[mt][nt], a1[mt], b3[nt]);
                    mma_f16(acc1[mt][nt], a3[mt], b1[nt]);
                    mma_f16(acc1[mt][nt], a2[mt], b2r[nt]);
                }
        }
        __syncthreads();
    }

    const float S = 1.f / 2048.f;
#pragma unroll
    for (int mt = 0; mt < 4; mt++) {
        int r0 = m0 + wm * 64 + mt * 16 + qid;
        int r1 = r0 + 8;
#pragma unroll
        for (int nt = 0; nt < 2; nt++) {
            int cb = n0 + wn * 16 + nt * 8 + rid * 2;
            float v0 = (acc0[mt][nt][0] + acc1[mt][nt][0] * S) * alpha;
            float v1 = (acc0[mt][nt][1] + acc1[mt][nt][1] * S) * alpha;
            float v2 = (acc0[mt][nt][2] + acc1[mt][nt][2] * S) * alpha;
            float v3 = (acc0[mt][nt][3] + acc1[mt][nt][3] * S) * alpha;
            if (MODE == 0) {
                *(float2*)(C + (size_t)r0 * ldc + cb) = make_float2(v0, v1);
                *(float2*)(C + (size_t)r1 * ldc + cb) = make_float2(v2, v3);
            } else {
                float b0 = bias[cb], b1 = bias[cb + 1];
                v0 += b0; v1 += b1; v2 += b0; v3 += b1;
                int h = cb >> 6, d = cb & 63;
                int b0i = r0 >> 11, s0i = r0 & (SS - 1);
                int b1i = r1 >> 11, s1i = r1 & (SS - 1);
                *(float2*)(C + (((size_t)(b0i * HH + h)) * SS + s0i) * DK + d) =
                    make_float2(v0, v1);
                *(float2*)(C + (((size_t)(b1i * HH + h)) * SS + s1i) * DK + d) =
                    make_float2(v2, v3);
            }
        }
    }
}

// ============================================================================
// fp16x3 split GEMM body (V projection): 22-bit accurate.
// ============================================================================
__device__ void hgemm3_body(const float* __restrict__ Ag,
                            const float* __restrict__ Bg,
                            float* __restrict__ Cg,
                            const float* __restrict__ bias,
                            int m0, int n0, char* smem_raw)
{
    typedef __half (*HArr)[40];
    HArr Ah = (HArr)(smem_raw);
    HArr Al = (HArr)(smem_raw + 10240);
    HArr Bh = (HArr)(smem_raw + 20480);
    HArr Bl = (HArr)(smem_raw + 30720);

    const int tid  = threadIdx.x;
    const int wid  = tid >> 5;
    const int lane = tid & 31;
    const int wm   = wid & 1;
    const int wn   = wid >> 1;
    const int qid  = lane >> 2;
    const int rid  = lane & 3;

    float acc[4][4][4];
#pragma unroll
    for (int i = 0; i < 4; i++)
#pragma unroll
        for (int j = 0; j < 4; j++)
#pragma unroll
            for (int t = 0; t < 4; t++) acc[i][j][t] = 0.f;

    for (int c = 0; c < DD / 32; c++) {
        const int k0 = c << 5;
        float4 va[4], vb[4];
#pragma unroll
        for (int i = 0; i < 4; i++) {
            int idx = tid + i * 256;
            int r = idx >> 3, cc = (idx & 7) << 2;
            va[i] = *(const float4*)(Ag + (size_t)(m0 + r) * DD + k0 + cc);
            vb[i] = *(const float4*)(Bg + (size_t)(n0 + r) * DD + k0 + cc);
        }
        __syncthreads();
#pragma unroll
        for (int i = 0; i < 4; i++) {
            int idx = tid + i * 256;
            int r = idx >> 3, cc = (idx & 7) << 2;
            float xa[4] = {va[i].x, va[i].y, va[i].z, va[i].w};
            float xb[4] = {vb[i].x, vb[i].y, vb[i].z, vb[i].w};
#pragma unroll
            for (int t = 0; t < 4; t++) {
                __half h = __float2half_rn(xa[t]);
                Ah[r][cc + t] = h;
                Al[r][cc + t] = __float2half_rn(xa[t] - __half2float(h));
                __half g = __float2half_rn(xb[t]);
                Bh[r][cc + t] = g;
                Bl[r][cc + t] = __float2half_rn(xb[t] - __half2float(g));
            }
        }
        __syncthreads();

#pragma unroll
        for (int kk = 0; kk < 32; kk += 16) {
            u32 ah[4][4], al[4][4], bh[4][2], bl[4][2];
#pragma unroll
            for (int mt = 0; mt < 4; mt++) {
                int row = wm * 64 + mt * 16 + qid;
                ah[mt][0] = *(const u32*)&Ah[row    ][kk + rid * 2];
                ah[mt][1] = *(const u32*)&Ah[row + 8][kk + rid * 2];
                ah[mt][2] = *(const u32*)&Ah[row    ][kk + rid * 2 + 8];
                ah[mt][3] = *(const u32*)&Ah[row + 8][kk + rid * 2 + 8];
                al[mt][0] = *(const u32*)&Al[row    ][kk + rid * 2];
                al[mt][1] = *(const u32*)&Al[row + 8][kk + rid * 2];
                al[mt][2] = *(const u32*)&Al[row    ][kk + rid * 2 + 8];
                al[mt][3] = *(const u32*)&Al[row + 8][kk + rid * 2 + 8];
            }
#pragma unroll
            for (int nt = 0; nt < 4; nt++) {
                int col = wn * 32 + nt * 8 + qid;
                bh[nt][0] = *(const u32*)&Bh[col][kk + rid * 2];
                bh[nt][1] = *(const u32*)&Bh[col][kk + rid * 2 + 8];
                bl[nt][0] = *(const u32*)&Bl[col][kk + rid * 2];
                bl[nt][1] = *(const u32*)&Bl[col][kk + rid * 2 + 8];
            }
#pragma unroll
            for (int mt = 0; mt < 4; mt++)
#pragma unroll
                for (int nt = 0; nt < 4; nt++) {
                    mma_f16(acc[mt][nt], ah[mt], bh[nt]);
                    mma_f16(acc[mt][nt], ah[mt], bl[nt]);
                    mma_f16(acc[mt][nt], al[mt], bh[nt]);
                }
        }
        __syncthreads();
    }

#pragma unroll
    for (int mt = 0; mt < 4; mt++) {
        int r0 = m0 + wm * 64 + mt * 16 + qid;
        int r1 = r0 + 8;
#pragma unroll
        for (int nt = 0; nt < 4; nt++) {
            int cb = n0 + wn * 32 + nt * 8 + rid * 2;
            float b0 = bias[cb], b1 = bias[cb + 1];
            float v0 = acc[mt][nt][0] + b0;
            float v1 = acc[mt][nt][1] + b1;
            float v2 = acc[mt][nt][2] + b0;
            float v3 = acc[mt][nt][3] + b1;
            int h = cb >> 6, d = cb & 63;
            int b0i = r0 >> 11, s0i = r0 & (SS - 1);
            int b1i = r1 >> 11, s1i = r1 & (SS - 1);
            *(float2*)(Cg + (((size_t)(b0i * HH + h)) * SS + s0i) * DK + d) =
                make_float2(v0, v1);
            *(float2*)(Cg + (((size_t)(b1i * HH + h)) * SS + s1i) * DK + d) =
                make_float2(v2, v3);
        }
    }
}

// ============================================================================
// QK projections, pipe-mixed with x%3 interleave: x%3==0 -> FFMA tile
// fi=x/3 (cols fi*128, 0..511); else fp16x6 tile hi=2*(x/3)+(x%3)-1
// (cols 512+hi*64). The +296 co-residency shift (mod 12 = 8) always pairs
// FFMA with HMMA: x%3==0 -> (x+8)%3==2.
// ============================================================================
__global__ __launch_bounds__(256, 2)
void qk_mixed(const float* __restrict__ q,  const float* __restrict__ Wq,
              const float* __restrict__ bq, float* __restrict__ qh,
              const float* __restrict__ k,  const float* __restrict__ Wk,
              const float* __restrict__ bk, float* __restrict__ kh)
{
    __shared__ __align__(16) char smem_raw[46080];
    const float* A  = blockIdx.z ? k  : q;
    const float* B  = blockIdx.z ? Wk : Wq;
    const float* bi = blockIdx.z ? bk : bq;
    float*       C  = blockIdx.z ? kh : qh;
    const int m0 = blockIdx.y * 128;
    const int x = blockIdx.x;

    if (x % 3 == 0) {
        float (*As)[8][128] = (float(*)[8][128])(smem_raw);
        float (*Bs)[8][128] = (float(*)[8][128])(smem_raw + 8192);
        ffma_tile<1>(A, B, C, bi, DD, DD, DD, 0, 1.f,
                     m0, (x / 3) * 128, As, Bs);
    } else {
        int hi = 2 * (x / 3) + (x % 3) - 1;   // 0..7
        f16x6_tile<1>(A, B, C, bi, DD, DD, DD, 0, 1.f,
                      m0, 512 + hi * 64, smem_raw);
    }
}

// ============================================================================
// Scores, pipe-mixed (x%3 interleave) + V projection (z==32).
// z<32: x%3==0 -> FFMA scores tile fi=x/3 (cols fi*128, 0..1023);
//       else fp16x6 tile hi=2*(x/3)+(x%3)-1 (cols 1024+hi*64).
// +296 shift (mod 24 = 8): x%3==0 -> (x+8)%3==2, FFMA always pairs w/ HMMA.
// ============================================================================
__global__ __launch_bounds__(256, 2)
void scores_vproj_mixed(const float* __restrict__ qh, const float* __restrict__ kh,
                        float* __restrict__ probs,
                        const float* __restrict__ v, const float* __restrict__ Wv,
                        const float* __restrict__ bv, float* __restrict__ vh)
{
    __shared__ __align__(16) char smem_raw[46080];

    if (blockIdx.z < 32) {
        const size_t z = blockIdx.z;
        const float* A = qh + z * SS * DK;
        const float* B = kh + z * SS * DK;
        float* C = probs + z * SS * SS;
        const int m0 = blockIdx.y * 128;
        const int x = blockIdx.x;
        if (x % 3 == 0) {
            float (*As)[8][128] = (float(*)[8][128])(smem_raw);
            float (*Bs)[8][128] = (float(*)[8][128])(smem_raw + 8192);
            ffma_tile<0>(A, B, C, nullptr, DK, DK, DK, SS, 0.125f,
                         m0, (x / 3) * 128, As, Bs);
        } else {
            int hi = 2 * (x / 3) + (x % 3) - 1;   // 0..15
            f16x6_tile<0>(A, B, C, nullptr, DK, DK, DK, SS, 0.125f,
                          m0, 1024 + hi * 64, smem_raw);
        }
    } else {
        int flat = blockIdx.y * 24 + blockIdx.x;   // 0..383
        if (flat >= 256) return;
        int m0 = (flat >> 3) * 128;
        int n0 = (flat & 7) * 128;
        hgemm3_body(v, Wv, vh, bv, m0, n0, smem_raw);
    }
}

// ============================================================================
// fp16 m16n8k16 NT GEMM (value path). A fp16, B fp16 or fp32(cvt), f32 acc.
// mode 3: AV -> fp16 concat scatter (z=(b,h)); mode 0: fp32 C + bias.
// ============================================================================
template<int NT, bool B_F32>
__global__ __launch_bounds__(256)
void hgemm_nt(const __half* __restrict__ Ag, const void* __restrict__ Bv,
              float* __restrict__ Cf, __half* __restrict__ Ch,
              const float* __restrict__ bias,
              int K, int lda, int ldb, int ldc,
              long long sA, long long sB,
              int mode)
{
    __shared__ __half As[128][56];
    __shared__ __half Bs[NT][56];

    const int tid  = threadIdx.x;
    const int wid  = tid >> 5;
    const int lane = tid & 31;
    const int wm   = wid & 1;
    const int wn   = wid >> 1;
    const int qid  = lane >> 2;
    const int rid  = lane & 3;

    constexpr int WN  = NT / 4;      // 32 or 16
    constexpr int NFR = WN / 8;      // 4 or 2

    const __half* A = Ag + (size_t)blockIdx.z * sA;
    const int m0 = blockIdx.y * 128;
    const int n0 = blockIdx.x * NT;

    float acc[4][NFR][4];
#pragma unroll
    for (int i = 0; i < 4; i++)
#pragma unroll
        for (int j = 0; j < NFR; j++)
#pragma unroll
            for (int t = 0; t < 4; t++) acc[i][j][t] = 0.f;

    const int nc = K >> 5;
    for (int c = 0; c < nc; c++) {
        const int k0 = c << 5;
        uint4 va[2];
#pragma unroll
        for (int i = 0; i < 2; i++) {
            int idx = tid + i * 256;
            int r = idx >> 2, seg = (idx & 3) << 3;
            va[i] = *(const uint4*)(A + (size_t)(m0 + r) * lda + k0 + seg);
        }
        if (B_F32) {
            const float* B = (const float*)Bv + (size_t)blockIdx.z * sB;
            constexpr int BI = (NT * 32) / (4 * 256);
            float4 vb[BI];
#pragma unroll
            for (int i = 0; i < BI; i++) {
                int idx = tid + i * 256;
                int r = idx >> 3, seg = (idx & 7) << 2;
                vb[i] = *(const float4*)(B + (size_t)(n0 + r) * ldb + k0 + seg);
            }
            __syncthreads();
#pragma unroll
            for (int i = 0; i < 2; i++) {
                int idx = tid + i * 256;
                int r = idx >> 2, seg = (idx & 3) << 3;
                *(uint4*)&As[r][seg] = va[i];
            }
#pragma unroll
            for (int i = 0; i < BI; i++) {
                int idx = tid + i * 256;
                int r = idx >> 3, seg = (idx & 7) << 2;
                *(__half2*)&Bs[r][seg]     = __floats2half2_rn(vb[i].x, vb[i].y);
                *(__half2*)&Bs[r][seg + 2] = __floats2half2_rn(vb[i].z, vb[i].w);
            }
        } else {
            const __half* B = (const __half*)Bv + (size_t)blockIdx.z * sB;
            constexpr int BI = (NT * 32) / (8 * 256) > 0 ? (NT * 32) / (8 * 256) : 1;
            uint4 vb[BI];
#pragma unroll
            for (int i = 0; i < BI; i++) {
                int idx = tid + i * 256;
                int r = idx >> 2, seg = (idx & 3) << 3;
                vb[i] = *(const uint4*)(B + (size_t)(n0 + r) * ldb + k0 + seg);
            }
            __syncthreads();
#pragma unroll
            for (int i = 0; i < 2; i++) {
                int idx = tid + i * 256;
                int r = idx >> 2, seg = (idx & 3) << 3;
                *(uint4*)&As[r][seg] = va[i];
            }
#pragma unroll
            for (int i = 0; i < BI; i++) {
                int idx = tid + i * 256;
                int r = idx >> 2, seg = (idx & 3) << 3;
                *(uint4*)&Bs[r][seg] = vb[i];
            }
        }
        __syncthreads();

#pragma unroll
        for (int kk = 0; kk < 32; kk += 16) {
            u32 af[4][4], bf[NFR][2];
#pragma unroll
            for (int mt = 0; mt < 4; mt++) {
                int row = wm * 64 + mt * 16 + qid;
                af[mt][0] = *(const u32*)&As[row    ][kk + rid * 2];
                af[mt][1] = *(const u32*)&As[row + 8][kk + rid * 2];
                af[mt][2] = *(const u32*)&As[row    ][kk + rid * 2 + 8];
                af[mt][3] = *(const u32*)&As[row + 8][kk + rid * 2 + 8];
            }
#pragma unroll
            for (int nt = 0; nt < NFR; nt++) {
                int col = wn * WN + nt * 8 + qid;
                bf[nt][0] = *(const u32*)&Bs[col][kk + rid * 2];
                bf[nt][1] = *(const u32*)&Bs[col][kk + rid * 2 + 8];
            }
#pragma unroll
            for (int mt = 0; mt < 4; mt++)
#pragma unroll
                for (int nt = 0; nt < NFR; nt++)
                    mma_f16(acc[mt][nt], af[mt], bf[nt]);
        }
        __syncthreads();
    }

#pragma unroll
    for (int mt = 0; mt < 4; mt++) {
        int r0 = m0 + wm * 64 + mt * 16 + qid;
        int r1 = r0 + 8;
#pragma unroll
        for (int nt = 0; nt < NFR; nt++) {
            int cb = n0 + wn * WN + nt * 8 + rid * 2;
            float v0 = acc[mt][nt][0];
            float v1 = acc[mt][nt][1];
            float v2 = acc[mt][nt][2];
            float v3 = acc[mt][nt][3];
            if (mode == 0) {
                float b0 = bias[cb], b1 = bias[cb + 1];
                *(float2*)(Cf + (size_t)r0 * ldc + cb) = make_float2(v0 + b0, v1 + b1);
                *(float2*)(Cf + (size_t)r1 * ldc + cb) = make_float2(v2 + b0, v3 + b1);
            } else {
                int z = blockIdx.z, b = z >> 4, h = z & 15;
                *(__half2*)(Ch + ((size_t)b * SS + r0) * DD + h * DK + cb) =
                    __floats2half2_rn(v0, v1);
                *(__half2*)(Ch + ((size_t)b * SS + r1) * DD + h * DK + cb) =
                    __floats2half2_rn(v2, v3);
            }
        }
    }
}

// ============================================================================
// Fused softmax + colsum partials; fp16 probs out. Two rows per iteration.
// ============================================================================
__global__ __launch_bounds__(256)
void softmax_colsum_kernel(const float* __restrict__ scores,
                           __half* __restrict__ probsh,
                           float* __restrict__ part)
{
    __shared__ float redA[2][8];
    __shared__ float redB[2][8];
    const int rb = blockIdx.x;   // 0..31
    const int bh = blockIdx.y;
    const int tid = threadIdx.x;
    const int wid = tid >> 5, lane = tid & 31;

    float cs[8];
#pragma unroll
    for (int i = 0; i < 8; i++) cs[i] = 0.f;

    for (int r = 0; r < 64; r += 2) {
        const float* row0 = scores + ((size_t)bh * SS + rb * 64 + r) * SS + tid * 8;
        const float* row1 = row0 + SS;
        float x0[8], x1[8];
        *(float4*)(x0)     = *(const float4*)(row0);
        *(float4*)(x0 + 4) = *(const float4*)(row0 + 4);
        *(float4*)(x1)     = *(const float4*)(row1);
        *(float4*)(x1 + 4) = *(const float4*)(row1 + 4);

        float m0 = x0[0], m1 = x1[0];
#pragma unroll
        for (int i = 1; i < 8; i++) { m0 = fmaxf(m0, x0[i]); m1 = fmaxf(m1, x1[i]); }
#pragma unroll
        for (int o = 16; o > 0; o >>= 1) {
            m0 = fmaxf(m0, __shfl_xor_sync(0xFFFFFFFF, m0, o));
            m1 = fmaxf(m1, __shfl_xor_sync(0xFFFFFFFF, m1, o));
        }
        if (lane == 0) { redA[0][wid] = m0; redA[1][wid] = m1; }
        __syncthreads();
        m0 = redA[0][0]; m1 = redA[1][0];
#pragma unroll
        for (int w = 1; w < 8; w++) {
            m0 = fmaxf(m0, redA[0][w]);
            m1 = fmaxf(m1, redA[1][w]);
        }

        float s0 = 0.f, s1 = 0.f;
#pragma unroll
        for (int i = 0; i < 8; i++) {
            x0[i] = __expf(x0[i] - m0); s0 += x0[i];
            x1[i] = __expf(x1[i] - m1); s1 += x1[i];
        }
#pragma unroll
        for (int o = 16; o > 0; o >>= 1) {
            s0 += __shfl_xor_sync(0xFFFFFFFF, s0, o);
            s1 += __shfl_xor_sync(0xFFFFFFFF, s1, o);
        }
        if (lane == 0) { redB[0][wid] = s0; redB[1][wid] = s1; }
        __syncthreads();
        s0 = redB[0][0]; s1 = redB[1][0];
#pragma unroll
        for (int w = 1; w < 8; w++) { s0 += redB[0][w]; s1 += redB[1][w]; }
        float inv0 = 1.0f / s0;
        float inv1 = 1.0f / s1;

        __half2 h0[4], h1[4];
#pragma unroll
        for (int i = 0; i < 8; i += 2) {
            float p0 = x0[i] * inv0, p1 = x0[i + 1] * inv0;
            cs[i] += p0; cs[i + 1] += p1;
            h0[i >> 1] = __floats2half2_rn(p0, p1);
        }
#pragma unroll
        for (int i = 0; i < 8; i += 2) {
            float p0 = x1[i] * inv1, p1 = x1[i + 1] * inv1;
            cs[i] += p0; cs[i + 1] += p1;
            h1[i >> 1] = __floats2half2_rn(p0, p1);
        }
        *(uint4*)(probsh + ((size_t)bh * SS + rb * 64 + r) * SS + tid * 8) =
            *(uint4*)h0;
        *(uint4*)(probsh + ((size_t)bh * SS + rb * 64 + r + 1) * SS + tid * 8) =
            *(uint4*)h1;
        __syncthreads();
    }
#pragma unroll
    for (int i = 0; i < 8; i++)
        part[((size_t)bh * 32 + rb) * SS + tid * 8 + i] = cs[i];
}

// ============================================================================
// Fused colsum-reduce + top-k mask (bitonic sort). One block per (b,h).
// ============================================================================
__global__ void topk_mask_kernel(const float* __restrict__ part,
                                 float* __restrict__ mask)
{
    __shared__ float s[SS];
    __shared__ float cs_sh[SS];
    const int bh = blockIdx.x;
    const int tid = threadIdx.x; // 1024

    for (int j = tid; j < SS; j += 1024) {
        float sum = 0.f;
#pragma unroll
        for (int rb = 0; rb < 32; rb++)
            sum += part[((size_t)bh * 32 + rb) * SS + j];
        s[j] = sum;
        cs_sh[j] = sum;
    }
    __syncthreads();

    for (int ksz = 2; ksz <= SS; ksz <<= 1) {
        for (int j = ksz >> 1; j > 0; j >>= 1) {
            for (int i = tid; i < SS; i += 1024) {
                int p = i ^ j;
                if (p > i) {
                    bool up = ((i & ksz) == 0);
                    float a = s[i], b = s[p];
                    if ((a > b) == up) { s[i] = b; s[p] = a; }
                }
            }
            __syncthreads();
        }
    }
    float thr = s[SS - KEEP];
    mask[bh * SS + tid]        = (cs_sh[tid]        >= thr) ? 1.f : 0.f;
    mask[bh * SS + tid + 1024] = (cs_sh[tid + 1024] >= thr) ? 1.f : 0.f;
}

// ============================================================================
// Masked transpose to fp16: vtmh[bh][d][s] = fp16(vh[bh][s][d] * mask[bh][s])
// ============================================================================
__global__ void vt_mask_kernel(const float* __restrict__ vh,
                               const float* __restrict__ mask,
                               __half* __restrict__ vtmh)
{
    __shared__ float t[32][33];
    const int bh = blockIdx.z;
    const int s0 = blockIdx.x * 32;
    const int d0 = blockIdx.y * 32;
    const int lx = threadIdx.x & 31;
    const int ly = threadIdx.x >> 5;
    for (int i = ly; i < 32; i += 8)
        t[i][lx] = vh[((size_t)bh * SS + s0 + i) * DK + d0 + lx] * mask[bh * SS + s0 + i];
    __syncthreads();
    for (int i = ly; i < 32; i += 8)
        vtmh[((size_t)bh * DK + d0 + i) * SS + s0 + lx] = __float2half_rn(t[lx][i]);
}

// ---------------------------------------------------------------------------
extern "C" void kernel_launch(void* const* d_in, const int* in_sizes, int n_in,
                              void* d_out, int out_size)
{
    (void)in_sizes; (void)n_in; (void)out_size;
    const float* q  = (const float*)d_in[0];
    const float* k  = (const float*)d_in[1];
    const float* v  = (const float*)d_in[2];
    const float* Wq = (const float*)d_in[3];
    const float* bq = (const float*)d_in[4];
    const float* Wk = (const float*)d_in[5];
    const float* bk = (const float*)d_in[6];
    const float* Wv = (const float*)d_in[7];
    const float* bv = (const float*)d_in[8];
    const float* Wo = (const float*)d_in[9];
    const float* bo = (const float*)d_in[10];
    float* out = (float*)d_out;

    float *qh, *kh, *vh, *probs, *part, *mask;
    __half *vtmh, *probsh, *concath;
    cudaGetSymbolAddress((void**)&qh,      g_qh);
    cudaGetSymbolAddress((void**)&kh,      g_kh);
    cudaGetSymbolAddress((void**)&vh,      g_vh);
    cudaGetSymbolAddress((void**)&vtmh,    g_vtmh);
    cudaGetSymbolAddress((void**)&probs,   g_probs);
    cudaGetSymbolAddress((void**)&probsh,  g_probsh);
    cudaGetSymbolAddress((void**)&part,    g_part);
    cudaGetSymbolAddress((void**)&mask,    g_mask);
    cudaGetSymbolAddress((void**)&concath, g_concath);

    // Q + K projections, FFMA/HMMA pipe-mixed (x%3 interleave)
    dim3 gqk(12, (BB * SS) / 128, 2);
    qk_mixed<<<gqk, 256>>>(q, Wq, bq, qh, k, Wk, bk, kh);

    // Scores (pipe-mixed, x%3 interleave) + V projection (z==32)
    dim3 gsv(24, SS / 128, BHN + 1);
    scores_vproj_mixed<<<gsv, 256>>>(qh, kh, probs, v, Wv, bv, vh);

    // Fused softmax + colsum partials (fp16 probs out)
    softmax_colsum_kernel<<<dim3(32, BHN), 256>>>(probs, probsh, part);

    // Fused colsum reduce + top-k mask
    topk_mask_kernel<<<BHN, 1024>>>(part, mask);

    // Masked V transpose -> fp16 vtmh[bh][d][s]
    vt_mask_kernel<<<dim3(SS / 32, DK / 32, BHN), 256>>>(vh, mask, vtmh);

    // AV (fp16 mma): per (b,h) 2048x64x2048 -> fp16 concat
    dim3 gav(1, SS / 128, BHN);
    hgemm_nt<64, false><<<gav, 256>>>(probsh, vtmh, nullptr, concath, nullptr,
                                      SS, SS, SS, 0,
                                      (long long)SS * SS, (long long)DK * SS, 3);

    // Output projection (fp16 mma, Wo cvt on load): fp32 out + bias
    dim3 gop(DD / 128, (BB * SS) / 128, 1);
    hgemm_nt<128, true><<<gop, 256>>>(concath, Wo, out, nullptr, bo,
                                      DD, DD, DD, DD, 0, 0, 0);
}